// round 11
// baseline (speedup 1.0000x reference)
#include <cuda_runtime.h>
#include <cuda_fp16.h>
#include <cstdint>

// Problem constants (B=2, S=4096, D=H=512), softmax scale = sqrt(512/8)=8.
#define Bsz 2
#define Sq  4096
#define Dd  512
#define Hh  512

// Scratch (device globals: allocation inside kernel_launch is forbidden).
__device__ __half g_xh [(size_t)Bsz * Sq * Dd], g_xl [(size_t)Bsz * Sq * Dd];
__device__ __half g_Wqh[Dd * Hh], g_Wql[Dd * Hh];
__device__ __half g_Wkh[Dd * Hh], g_Wkl[Dd * Hh];
__device__ __half g_Wvh[Dd * Hh], g_Wvl[Dd * Hh];
__device__ __half g_Wmh[Hh * Hh], g_Wml[Hh * Hh];
__device__ __half g_qh [(size_t)Bsz * Sq * Hh], g_ql [(size_t)Bsz * Sq * Hh];
__device__ __half g_kh [(size_t)Bsz * Sq * Hh], g_kl [(size_t)Bsz * Sq * Hh];
__device__ float  g_v  [(size_t)Bsz * Sq * Hh];
__device__ __half g_vth[(size_t)Bsz * Sq * Hh], g_vtl[(size_t)Bsz * Sq * Hh];
__device__ float  g_sc [(size_t)Bsz * Sq * Sq];                    // 128 MB
__device__ __half g_ph [(size_t)Bsz * Sq * Sq];                    // 64 MB (unnormalized probs)
__device__ float  g_linv[(size_t)Bsz * Sq];                        // 1/rowsum
__device__ __half g_ath[(size_t)Bsz * Sq * Hh], g_atl[(size_t)Bsz * Sq * Hh];

// ---------------------------------------------------------------------------
// helpers
// ---------------------------------------------------------------------------
__device__ __forceinline__ uint32_t smem_u32(const void* p) {
    uint32_t a;
    asm("{ .reg .u64 t; cvta.to.shared.u64 t, %1; cvt.u32.u64 %0, t; }"
        : "=r"(a) : "l"(p));
    return a;
}
__device__ __forceinline__ void cp16(uint32_t smem, const void* g) {
    asm volatile("cp.async.cg.shared.global [%0], [%1], 16;"
                 :: "r"(smem), "l"(g) : "memory");
}
#define CP_COMMIT() asm volatile("cp.async.commit_group;" ::: "memory")
#define CP_WAIT(n)  asm volatile("cp.async.wait_group %0;" :: "n"(n) : "memory")

// m16n8k16 fp16 mma, fp32 accum. row.col => both operands K-major (NT GEMM).
__device__ __forceinline__ void mma16(float* c, const uint32_t* a, const uint32_t* b) {
    asm volatile(
        "mma.sync.aligned.m16n8k16.row.col.f32.f16.f16.f32 "
        "{%0,%1,%2,%3}, {%4,%5,%6,%7}, {%8,%9}, {%0,%1,%2,%3};"
        : "+f"(c[0]), "+f"(c[1]), "+f"(c[2]), "+f"(c[3])
        : "r"(a[0]), "r"(a[1]), "r"(a[2]), "r"(a[3]), "r"(b[0]), "r"(b[1]));
}

// ---------------------------------------------------------------------------
// fp16x3 GEMM:  C = rowscale[r] * (scale * (A @ W^T) + bscale * bias)
// A as (Ah, Al) fp16 pair (Al may be null -> 2-term mode), W as (Wh, Wl).
// Output fp32 Cf and/or fp16 pair (Ch, Cl). CTA tile 128x128, K-chunk 64.
// 512 threads = 16 warps (4 M x 4 N), warp tile 32x32. smem stride 36 b32.
//
// pair_diag mode (PV): gridDim.y covers HALF the row tiles; each CTA runs two
// row-tiles (mb, nmb-1-mb) sequentially. With diag_kstart, per-tile K lengths
// sum to a constant -> perfectly uniform CTA cost, single wave.
// ---------------------------------------------------------------------------
#define BM 128
#define BN 128
#define KC 64
#define RS 36
#define PART (128 * RS)
#define STAGE (4 * PART)
#define SMEM_SZ (2 * STAGE * 4)        // 144 KB

__global__ __launch_bounds__(512, 1)
void k_hgemm(const __half* __restrict__ Ah, const __half* __restrict__ Al,
             const __half* __restrict__ Wh, const __half* __restrict__ Wl,
             const float* __restrict__ bias, const float* __restrict__ rowscale,
             float* __restrict__ Cf, __half* __restrict__ Ch, __half* __restrict__ Cl,
             int M, int N, int K, float scale, float bscale,
             long long sA, long long sW, long long sC,
             int skip_lower, int diag_kstart, int pair_diag)
{
    int nb = blockIdx.x, bz = blockIdx.z;
    int mb = blockIdx.y;
    if (skip_lower && nb < mb) return;          // block entirely masked (j < i)
    int hasAl = (Al != 0);
    Ah += (size_t)bz * sA;  if (hasAl) Al += (size_t)bz * sA;
    Wh += (size_t)bz * sW;  Wl += (size_t)bz * sW;
    if (Cf) Cf += (size_t)bz * sC;
    if (Ch) { Ch += (size_t)bz * sC; Cl += (size_t)bz * sC; }
    if (rowscale) rowscale += (size_t)bz * M;

    extern __shared__ uint32_t sm32[];
    uint32_t smb = smem_u32(sm32);

    int tid  = threadIdx.x;
    int warp = tid >> 5, lane = tid & 31;
    int wm = warp >> 2, wn = warp & 3;
    int g  = lane >> 2, q4 = lane & 3;
    int n0 = nb * BN;
    int lr  = tid >> 3;
    int seg = tid & 7;

    int nmb  = M / BM;
    int nrep = pair_diag ? 2 : 1;

    for (int rep = 0; rep < nrep; rep++) {
        int mbe = pair_diag ? (rep == 0 ? mb : (nmb - 1 - mb)) : mb;
        int m0  = mbe * BM;
        int kt0 = diag_kstart ? m0 : 0;
        int nch = (K - kt0) / KC;

        float acc[2][4][4];
        #pragma unroll
        for (int i = 0; i < 2; i++)
            #pragma unroll
            for (int j = 0; j < 4; j++)
                #pragma unroll
                for (int r = 0; r < 4; r++) acc[i][j][r] = 0.f;

        auto load_stage = [&](uint32_t sb, int kt) {
            #pragma unroll
            for (int j = 0; j < 2; j++) {
                int row = j * 64 + lr;
                uint32_t so = (uint32_t)(row * RS) * 4 + seg * 16;
                size_t ga = (size_t)(m0 + row) * K + kt + seg * 8;
                size_t gw = (size_t)(n0 + row) * K + kt + seg * 8;
                cp16(sb + so,                 Ah + ga);
                if (hasAl) cp16(sb + PART * 4 + so, Al + ga);
                cp16(sb + 2 * PART * 4 + so,  Wh + gw);
                cp16(sb + 3 * PART * 4 + so,  Wl + gw);
            }
        };

        load_stage(smb, kt0);
        CP_COMMIT();

        for (int ic = 0; ic < nch; ic++) {
            if (ic + 1 < nch) {
                load_stage(smb + ((ic + 1) & 1) * STAGE * 4, kt0 + (ic + 1) * KC);
                CP_COMMIT();
                CP_WAIT(1);
            } else {
                CP_WAIT(0);
            }
            __syncthreads();

            const uint32_t* S0 = sm32 + (ic & 1) * STAGE;
            const uint32_t* Ahs = S0;
            const uint32_t* Als = S0 + PART;
            const uint32_t* Bhs = S0 + 2 * PART;
            const uint32_t* Bls = S0 + 3 * PART;

            #pragma unroll
            for (int ks = 0; ks < 4; ks++) {
                int c0 = ks * 8 + q4;
                uint32_t ah[2][4], al[2][4];
                #pragma unroll
                for (int tm = 0; tm < 2; tm++) {
                    int r = wm * 32 + tm * 16 + g;
                    ah[tm][0] = Ahs[r * RS + c0];
                    ah[tm][1] = Ahs[(r + 8) * RS + c0];
                    ah[tm][2] = Ahs[r * RS + c0 + 4];
                    ah[tm][3] = Ahs[(r + 8) * RS + c0 + 4];
                    if (hasAl) {
                        al[tm][0] = Als[r * RS + c0];
                        al[tm][1] = Als[(r + 8) * RS + c0];
                        al[tm][2] = Als[r * RS + c0 + 4];
                        al[tm][3] = Als[(r + 8) * RS + c0 + 4];
                    }
                }
                #pragma unroll
                for (int tn = 0; tn < 4; tn++) {
                    int n = wn * 32 + tn * 8 + g;
                    uint32_t bh[2], bl[2];
                    bh[0] = Bhs[n * RS + c0];
                    bh[1] = Bhs[n * RS + c0 + 4];
                    bl[0] = Bls[n * RS + c0];
                    bl[1] = Bls[n * RS + c0 + 4];
                    #pragma unroll
                    for (int tm = 0; tm < 2; tm++) {
                        mma16(acc[tm][tn], ah[tm], bh);            // hi*hi
                        mma16(acc[tm][tn], ah[tm], bl);            // hi*lo
                        if (hasAl) mma16(acc[tm][tn], al[tm], bh); // lo*hi
                    }
                }
            }
            __syncthreads();
        }

        // ---- epilogue ----
        #pragma unroll
        for (int tm = 0; tm < 2; tm++) {
            int r = m0 + wm * 32 + tm * 16 + g;
            float rs0 = 1.f, rs1 = 1.f;
            if (rowscale) { rs0 = rowscale[r]; rs1 = rowscale[r + 8]; }
            #pragma unroll
            for (int tn = 0; tn < 4; tn++) {
                int cc = n0 + wn * 32 + tn * 8 + q4 * 2;
                float bv0 = 0.f, bv1 = 0.f;
                if (bias) {
                    bv0 = bscale * __ldg(bias + cc);
                    bv1 = bscale * __ldg(bias + cc + 1);
                }
                float v00 = (scale * acc[tm][tn][0] + bv0) * rs0;
                float v01 = (scale * acc[tm][tn][1] + bv1) * rs0;
                float v10 = (scale * acc[tm][tn][2] + bv0) * rs1;
                float v11 = (scale * acc[tm][tn][3] + bv1) * rs1;
                if (Cf) {
                    *(float2*)(Cf + (size_t)r * N + cc)       = make_float2(v00, v01);
                    *(float2*)(Cf + (size_t)(r + 8) * N + cc) = make_float2(v10, v11);
                }
                if (Ch) {
                    __half h00 = __float2half_rn(v00), h01 = __float2half_rn(v01);
                    __half h10 = __float2half_rn(v10), h11 = __float2half_rn(v11);
                    *(__half2*)(Ch + (size_t)r * N + cc)       = __halves2half2(h00, h01);
                    *(__half2*)(Ch + (size_t)(r + 8) * N + cc) = __halves2half2(h10, h11);
                    *(__half2*)(Cl + (size_t)r * N + cc) = __halves2half2(
                        __float2half_rn(v00 - __half2float(h00)),
                        __float2half_rn(v01 - __half2float(h01)));
                    *(__half2*)(Cl + (size_t)(r + 8) * N + cc) = __halves2half2(
                        __float2half_rn(v10 - __half2float(h10)),
                        __float2half_rn(v11 - __half2float(h11)));
                }
            }
        }
        if (rep + 1 < nrep) __syncthreads();   // smem handoff between tiles
    }
}

// ---------------------------------------------------------------------------
// Split fp32 -> fp16 hi/lo pair.
// ---------------------------------------------------------------------------
__global__ __launch_bounds__(256)
void k_split(const float* __restrict__ x, __half* __restrict__ h,
             __half* __restrict__ l, int n)
{
    for (int i = blockIdx.x * 256 + threadIdx.x; i < n; i += gridDim.x * 256) {
        float v = x[i];
        __half hh = __float2half_rn(v);
        h[i] = hh;
        l[i] = __float2half_rn(v - __half2float(hh));
    }
}

// ---------------------------------------------------------------------------
// 2-pass row softmax: single exp per element. Writes UNNORMALIZED p=exp(s-m)
// as fp16 for j in [i, S), zeros for [i_tile, i), and inv_l = 1/sum per row.
// Normalization is applied in the PV epilogue via rowscale.
// ---------------------------------------------------------------------------
__global__ __launch_bounds__(256)
void k_softmax(const float* __restrict__ Sc, __half* __restrict__ Ph,
               float* __restrict__ Linv)
{
    int i = blockIdx.x;
    int b = blockIdx.y;
    size_t off = ((size_t)b * Sq + i) * Sq;
    const float* row = Sc + off;
    __half* ph = Ph + off;
    int t = threadIdx.x;
    __shared__ float red[256];

    // pass 1: max over [i, S)
    float m = -3.402823466e38f;
    for (int j = i + t; j < Sq; j += 256) m = fmaxf(m, row[j]);
    red[t] = m; __syncthreads();
    for (int s = 128; s > 0; s >>= 1) {
        if (t < s) red[t] = fmaxf(red[t], red[t + s]);
        __syncthreads();
    }
    m = red[0];
    __syncthreads();

    // pass 2: exp once, write unnormalized p, accumulate sum
    float l = 0.f;
    for (int j = i + t; j < Sq; j += 256) {
        float e = __expf(row[j] - m);
        l += e;
        ph[j] = __float2half_rn(e);
    }
    // zero the masked prefix within this row's PV k-tile
    int i0 = i & ~(BM - 1);
    for (int j = i0 + t; j < i; j += 256) ph[j] = __float2half_rn(0.f);

    red[t] = l; __syncthreads();
    for (int s = 128; s > 0; s >>= 1) {
        if (t < s) red[t] += red[t + s];
        __syncthreads();
    }
    if (t == 0) Linv[(size_t)b * Sq + i] = 1.0f / red[0];
}

// ---------------------------------------------------------------------------
// Transpose v [S,H] -> vt [H,S] per batch, splitting to fp16 hi/lo.
// ---------------------------------------------------------------------------
__global__ __launch_bounds__(256)
void k_transpose_split(const float* __restrict__ V, __half* __restrict__ Th,
                       __half* __restrict__ Tl)
{
    __shared__ float t[32][33];
    int bz = blockIdx.z;
    const float* Vb = V + (size_t)bz * Sq * Hh;
    __half* Hb = Th + (size_t)bz * Sq * Hh;
    __half* Lb = Tl + (size_t)bz * Sq * Hh;
    int c0 = blockIdx.x * 32, r0 = blockIdx.y * 32;
    int tx = threadIdx.x & 31, ty = threadIdx.x >> 5;
    #pragma unroll
    for (int i = ty; i < 32; i += 8)
        t[i][tx] = Vb[(size_t)(r0 + i) * Hh + c0 + tx];
    __syncthreads();
    #pragma unroll
    for (int i = ty; i < 32; i += 8) {
        float v = t[tx][i];
        __half h = __float2half_rn(v);
        size_t o = (size_t)(c0 + i) * Sq + r0 + tx;
        Hb[o] = h;
        Lb[o] = __float2half_rn(v - __half2float(h));
    }
}

// ---------------------------------------------------------------------------
extern "C" void kernel_launch(void* const* d_in, const int* in_sizes, int n_in,
                              void* d_out, int out_size)
{
    (void)in_sizes; (void)n_in; (void)out_size;
    const float* x  = (const float*)d_in[0];
    const float* Wq = (const float*)d_in[1];
    const float* bq = (const float*)d_in[2];
    const float* Wk = (const float*)d_in[3];
    const float* bk = (const float*)d_in[4];
    const float* Wv = (const float*)d_in[5];
    const float* bv = (const float*)d_in[6];
    const float* Wm = (const float*)d_in[7];
    const float* bm = (const float*)d_in[8];
    float* out = (float*)d_out;

    __half *xh, *xl, *Wqh, *Wql, *Wkh, *Wkl, *Wvh, *Wvl, *Wmh, *Wml;
    __half *qh, *ql, *kh, *kl, *vth, *vtl, *ph, *ath, *atl;
    float *v, *sc, *linv;
    cudaGetSymbolAddress((void**)&xh,  g_xh);  cudaGetSymbolAddress((void**)&xl,  g_xl);
    cudaGetSymbolAddress((void**)&Wqh, g_Wqh); cudaGetSymbolAddress((void**)&Wql, g_Wql);
    cudaGetSymbolAddress((void**)&Wkh, g_Wkh); cudaGetSymbolAddress((void**)&Wkl, g_Wkl);
    cudaGetSymbolAddress((void**)&Wvh, g_Wvh); cudaGetSymbolAddress((void**)&Wvl, g_Wvl);
    cudaGetSymbolAddress((void**)&Wmh, g_Wmh); cudaGetSymbolAddress((void**)&Wml, g_Wml);
    cudaGetSymbolAddress((void**)&qh,  g_qh);  cudaGetSymbolAddress((void**)&ql,  g_ql);
    cudaGetSymbolAddress((void**)&kh,  g_kh);  cudaGetSymbolAddress((void**)&kl,  g_kl);
    cudaGetSymbolAddress((void**)&v,   g_v);
    cudaGetSymbolAddress((void**)&vth, g_vth); cudaGetSymbolAddress((void**)&vtl, g_vtl);
    cudaGetSymbolAddress((void**)&sc,  g_sc);
    cudaGetSymbolAddress((void**)&ph,  g_ph);
    cudaGetSymbolAddress((void**)&linv,g_linv);
    cudaGetSymbolAddress((void**)&ath, g_ath); cudaGetSymbolAddress((void**)&atl, g_atl);

    cudaFuncSetAttribute(k_hgemm, cudaFuncAttributeMaxDynamicSharedMemorySize, SMEM_SZ);

    dim3 blk(512);

    // Split inputs once.
    k_split<<<2048, 256>>>(x,  xh,  xl,  Bsz * Sq * Dd);
    k_split<<<256,  256>>>(Wq, Wqh, Wql, Dd * Hh);
    k_split<<<256,  256>>>(Wk, Wkh, Wkl, Dd * Hh);
    k_split<<<256,  256>>>(Wv, Wvh, Wvl, Dd * Hh);
    k_split<<<256,  256>>>(Wm, Wmh, Wml, Hh * Hh);

    dim3 gproj(Hh / BN, (Bsz * Sq) / BM, 1);      // 4 x 64

    // Projections (softmax 1/8 folded into q, incl. its bias).
    k_hgemm<<<gproj, blk, SMEM_SZ>>>(xh, xl, Wqh, Wql, bq, (float*)0, (float*)0, qh, ql,
                                     Bsz * Sq, Hh, Dd, 0.125f, 0.125f, 0, 0, 0, 0, 0, 0);
    k_hgemm<<<gproj, blk, SMEM_SZ>>>(xh, xl, Wkh, Wkl, bk, (float*)0, (float*)0, kh, kl,
                                     Bsz * Sq, Hh, Dd, 1.0f, 1.0f, 0, 0, 0, 0, 0, 0);
    k_hgemm<<<gproj, blk, SMEM_SZ>>>(xh, xl, Wvh, Wvl, bv, (float*)0, v, (__half*)0, (__half*)0,
                                     Bsz * Sq, Hh, Dd, 1.0f, 1.0f, 0, 0, 0, 0, 0, 0);

    // Scores (fp32), upper-triangular blocks only (nb >= mb).
    k_hgemm<<<dim3(Sq / BN, Sq / BM, Bsz), blk, SMEM_SZ>>>(
        qh, ql, kh, kl, (const float*)0, (float*)0, sc, (__half*)0, (__half*)0,
        Sq, Sq, Hh, 1.0f, 0.0f,
        (long long)Sq * Hh, (long long)Sq * Hh, (long long)Sq * Sq, 1, 0, 0);

    // 2-pass softmax -> unnormalized fp16 probs + inv rowsum.
    k_softmax<<<dim3(Sq, Bsz), 256>>>(sc, ph, linv);

    // vt = v^T (split), then attn = (P @ v) * inv_l, 2-term.
    // pair_diag: each CTA runs row-tiles (mb, 31-mb); per-CTA K sums constant
    // (4224) -> 128 uniform CTAs, single wave, no straggler tail.
    k_transpose_split<<<dim3(Hh / 32, Sq / 32, Bsz), 256>>>(v, vth, vtl);
    k_hgemm<<<dim3(Hh / BN, Sq / (2 * BM), Bsz), blk, SMEM_SZ>>>(
        ph, (__half*)0, vth, vtl, (const float*)0, linv, (float*)0, ath, atl,
        Sq, Hh, Sq, 1.0f, 0.0f,
        (long long)Sq * Sq, (long long)Sq * Hh, (long long)Sq * Hh, 0, 1, 1);

    // out = 8 * attn @ Wm^T + bm  (NUM_HEADS folded into scale).
    k_hgemm<<<gproj, blk, SMEM_SZ>>>(ath, atl, Wmh, Wml, bm, (float*)0, out, (__half*)0, (__half*)0,
                                     Bsz * Sq, Hh, Dd, 8.0f, 1.0f, 0, 0, 0, 0, 0, 0);
}

// round 12
// speedup vs baseline: 1.0810x; 1.0810x over previous
#include <cuda_runtime.h>
#include <cuda_fp16.h>
#include <cstdint>

// Problem constants (B=2, S=4096, D=H=512), softmax scale = sqrt(512/8)=8.
#define Bsz 2
#define Sq  4096
#define Dd  512
#define Hh  512

// Scratch (device globals: allocation inside kernel_launch is forbidden).
__device__ __half g_xh [(size_t)Bsz * Sq * Dd], g_xl [(size_t)Bsz * Sq * Dd];
__device__ __half g_Wqh[Dd * Hh], g_Wql[Dd * Hh];
__device__ __half g_Wkh[Dd * Hh], g_Wkl[Dd * Hh];
__device__ __half g_Wvh[Dd * Hh], g_Wvl[Dd * Hh];
__device__ __half g_Wmh[Hh * Hh], g_Wml[Hh * Hh];
__device__ __half g_qh [(size_t)Bsz * Sq * Hh], g_ql [(size_t)Bsz * Sq * Hh];
__device__ __half g_kh [(size_t)Bsz * Sq * Hh], g_kl [(size_t)Bsz * Sq * Hh];
__device__ float  g_v  [(size_t)Bsz * Sq * Hh];
__device__ __half g_vth[(size_t)Bsz * Sq * Hh], g_vtl[(size_t)Bsz * Sq * Hh];
__device__ float  g_sc [(size_t)Bsz * Sq * Sq];                    // 128 MB
__device__ __half g_ph [(size_t)Bsz * Sq * Sq];                    // 64 MB (unnormalized probs)
__device__ float  g_linv[(size_t)Bsz * Sq];                        // 1/rowsum
__device__ __half g_ath[(size_t)Bsz * Sq * Hh], g_atl[(size_t)Bsz * Sq * Hh];

// ---------------------------------------------------------------------------
// helpers
// ---------------------------------------------------------------------------
__device__ __forceinline__ uint32_t smem_u32(const void* p) {
    uint32_t a;
    asm("{ .reg .u64 t; cvta.to.shared.u64 t, %1; cvt.u32.u64 %0, t; }"
        : "=r"(a) : "l"(p));
    return a;
}
__device__ __forceinline__ void cp16(uint32_t smem, const void* g) {
    asm volatile("cp.async.cg.shared.global [%0], [%1], 16;"
                 :: "r"(smem), "l"(g) : "memory");
}
#define CP_COMMIT() asm volatile("cp.async.commit_group;" ::: "memory")
#define CP_WAIT(n)  asm volatile("cp.async.wait_group %0;" :: "n"(n) : "memory")

// ldmatrix: 4x m8n8 b16 matrices from shared (one address per lane).
#define LDSM4(r, addr)                                                        \
    asm volatile("ldmatrix.sync.aligned.m8n8.x4.shared.b16 "                  \
                 "{%0,%1,%2,%3}, [%4];"                                       \
                 : "=r"((r)[0]), "=r"((r)[1]), "=r"((r)[2]), "=r"((r)[3])     \
                 : "r"(addr))

// m16n8k16 fp16 mma, fp32 accum. row.col => both operands K-major (NT GEMM).
__device__ __forceinline__ void mma16(float* c, const uint32_t* a, const uint32_t* b) {
    asm volatile(
        "mma.sync.aligned.m16n8k16.row.col.f32.f16.f16.f32 "
        "{%0,%1,%2,%3}, {%4,%5,%6,%7}, {%8,%9}, {%0,%1,%2,%3};"
        : "+f"(c[0]), "+f"(c[1]), "+f"(c[2]), "+f"(c[3])
        : "r"(a[0]), "r"(a[1]), "r"(a[2]), "r"(a[3]), "r"(b[0]), "r"(b[1]));
}

// ---------------------------------------------------------------------------
// fp16x3 GEMM:  C = rowscale[r] * (scale * (A @ W^T) + bscale * bias)
// A as (Ah, Al) fp16 pair (Al may be null -> 2-term mode), W as (Wh, Wl).
// Output fp32 Cf and/or fp16 pair (Ch, Cl). CTA tile 128x128, K-chunk 64.
// 512 threads = 16 warps (4 M x 4 N), warp tile 32x32. smem stride 36 b32;
// fragments loaded via ldmatrix.x4 (conflict-free: bank = 4*row mod 32).
// ---------------------------------------------------------------------------
#define BM 128
#define BN 128
#define KC 64
#define RS 36
#define PART (128 * RS)
#define PART4 (PART * 4)
#define STAGE (4 * PART)
#define SMEM_SZ (2 * STAGE * 4)        // 144 KB

__global__ __launch_bounds__(512, 1)
void k_hgemm(const __half* __restrict__ Ah, const __half* __restrict__ Al,
             const __half* __restrict__ Wh, const __half* __restrict__ Wl,
             const float* __restrict__ bias, const float* __restrict__ rowscale,
             float* __restrict__ Cf, __half* __restrict__ Ch, __half* __restrict__ Cl,
             int M, int N, int K, float scale, float bscale,
             long long sA, long long sW, long long sC,
             int skip_lower, int diag_kstart)
{
    int nb = blockIdx.x, bz = blockIdx.z;
    int mb = blockIdx.y;
    if (skip_lower && nb < mb) return;          // block entirely masked (j < i)
    int hasAl = (Al != 0);
    Ah += (size_t)bz * sA;  if (hasAl) Al += (size_t)bz * sA;
    Wh += (size_t)bz * sW;  Wl += (size_t)bz * sW;
    if (Cf) Cf += (size_t)bz * sC;
    if (Ch) { Ch += (size_t)bz * sC; Cl += (size_t)bz * sC; }
    if (rowscale) rowscale += (size_t)bz * M;

    extern __shared__ uint32_t sm32[];
    uint32_t smb = smem_u32(sm32);

    int tid  = threadIdx.x;
    int warp = tid >> 5, lane = tid & 31;
    int wm = warp >> 2, wn = warp & 3;
    int g  = lane >> 2, q4 = lane & 3;
    int m0 = mb * BM, n0 = nb * BN;

    int kt0 = diag_kstart ? m0 : 0;
    int nch = (K - kt0) / KC;

    float acc[2][4][4];
    #pragma unroll
    for (int i = 0; i < 2; i++)
        #pragma unroll
        for (int j = 0; j < 4; j++)
            #pragma unroll
            for (int r = 0; r < 4; r++) acc[i][j][r] = 0.f;

    int lr  = tid >> 3;
    int seg = tid & 7;

    // per-lane ldmatrix byte offsets (within a stage), k-step adds ks*32B
    // A (x4 = rows r..r+15, k0-7 then k8-15):
    //   lanes 0-15 -> rows (lane&15) @k0-7; lanes 16-31 -> same rows @k8-15
    uint32_t a_off[2];
    #pragma unroll
    for (int tm = 0; tm < 2; tm++) {
        int row = wm * 32 + tm * 16 + (lane & 15);
        a_off[tm] = (uint32_t)(row * RS + (lane >> 4) * 4) * 4;
    }
    // B (x4 = two n8 tiles x {k0-7, k8-15}):
    //   lanes 0-7: n0-7 @k0; 8-15: n0-7 @k8; 16-23: n8-15 @k0; 24-31: n8-15 @k8
    uint32_t b_off[2];
    #pragma unroll
    for (int p = 0; p < 2; p++) {
        int row = wn * 32 + p * 16 + (lane & 7) + ((lane >> 4) & 1) * 8;
        b_off[p] = (uint32_t)(row * RS + ((lane >> 3) & 1) * 4) * 4;
    }

    auto load_stage = [&](uint32_t sb, int kt) {
        #pragma unroll
        for (int j = 0; j < 2; j++) {
            int row = j * 64 + lr;
            uint32_t so = (uint32_t)(row * RS) * 4 + seg * 16;
            size_t ga = (size_t)(m0 + row) * K + kt + seg * 8;
            size_t gw = (size_t)(n0 + row) * K + kt + seg * 8;
            cp16(sb + so,              Ah + ga);
            if (hasAl) cp16(sb + PART4 + so, Al + ga);
            cp16(sb + 2 * PART4 + so,  Wh + gw);
            cp16(sb + 3 * PART4 + so,  Wl + gw);
        }
    };

    load_stage(smb, kt0);
    CP_COMMIT();

    for (int ic = 0; ic < nch; ic++) {
        if (ic + 1 < nch) {
            load_stage(smb + ((ic + 1) & 1) * STAGE * 4, kt0 + (ic + 1) * KC);
            CP_COMMIT();
            CP_WAIT(1);
        } else {
            CP_WAIT(0);
        }
        __syncthreads();

        uint32_t sbase = smb + (ic & 1) * STAGE * 4;

        #pragma unroll
        for (int ks = 0; ks < 4; ks++) {
            uint32_t ko = (uint32_t)ks * 32;      // 8 u32 = 32 bytes per k16
            uint32_t ah[2][4], al[2][4];
            #pragma unroll
            for (int tm = 0; tm < 2; tm++) {
                LDSM4(ah[tm], sbase + a_off[tm] + ko);
                if (hasAl) LDSM4(al[tm], sbase + PART4 + a_off[tm] + ko);
            }
            uint32_t bh[2][4], bl[2][4];
            #pragma unroll
            for (int p = 0; p < 2; p++) {
                LDSM4(bh[p], sbase + 2 * PART4 + b_off[p] + ko);
                LDSM4(bl[p], sbase + 3 * PART4 + b_off[p] + ko);
            }
            #pragma unroll
            for (int tn = 0; tn < 4; tn++) {
                const uint32_t* bhp = &bh[tn >> 1][(tn & 1) * 2];
                const uint32_t* blp = &bl[tn >> 1][(tn & 1) * 2];
                #pragma unroll
                for (int tm = 0; tm < 2; tm++) {
                    mma16(acc[tm][tn], ah[tm], bhp);            // hi*hi
                    mma16(acc[tm][tn], ah[tm], blp);            // hi*lo
                    if (hasAl) mma16(acc[tm][tn], al[tm], bhp); // lo*hi
                }
            }
        }
        __syncthreads();
    }

    // ---- epilogue ----
    #pragma unroll
    for (int tm = 0; tm < 2; tm++) {
        int r = m0 + wm * 32 + tm * 16 + g;
        float rs0 = 1.f, rs1 = 1.f;
        if (rowscale) { rs0 = rowscale[r]; rs1 = rowscale[r + 8]; }
        #pragma unroll
        for (int tn = 0; tn < 4; tn++) {
            int cc = n0 + wn * 32 + tn * 8 + q4 * 2;
            float bv0 = 0.f, bv1 = 0.f;
            if (bias) {
                bv0 = bscale * __ldg(bias + cc);
                bv1 = bscale * __ldg(bias + cc + 1);
            }
            float v00 = (scale * acc[tm][tn][0] + bv0) * rs0;
            float v01 = (scale * acc[tm][tn][1] + bv1) * rs0;
            float v10 = (scale * acc[tm][tn][2] + bv0) * rs1;
            float v11 = (scale * acc[tm][tn][3] + bv1) * rs1;
            if (Cf) {
                *(float2*)(Cf + (size_t)r * N + cc)       = make_float2(v00, v01);
                *(float2*)(Cf + (size_t)(r + 8) * N + cc) = make_float2(v10, v11);
            }
            if (Ch) {
                __half h00 = __float2half_rn(v00), h01 = __float2half_rn(v01);
                __half h10 = __float2half_rn(v10), h11 = __float2half_rn(v11);
                *(__half2*)(Ch + (size_t)r * N + cc)       = __halves2half2(h00, h01);
                *(__half2*)(Ch + (size_t)(r + 8) * N + cc) = __halves2half2(h10, h11);
                *(__half2*)(Cl + (size_t)r * N + cc) = __halves2half2(
                    __float2half_rn(v00 - __half2float(h00)),
                    __float2half_rn(v01 - __half2float(h01)));
                *(__half2*)(Cl + (size_t)(r + 8) * N + cc) = __halves2half2(
                    __float2half_rn(v10 - __half2float(h10)),
                    __float2half_rn(v11 - __half2float(h11)));
            }
        }
    }
}

// ---------------------------------------------------------------------------
// Split fp32 -> fp16 hi/lo pair.
// ---------------------------------------------------------------------------
__global__ __launch_bounds__(256)
void k_split(const float* __restrict__ x, __half* __restrict__ h,
             __half* __restrict__ l, int n)
{
    for (int i = blockIdx.x * 256 + threadIdx.x; i < n; i += gridDim.x * 256) {
        float v = x[i];
        __half hh = __float2half_rn(v);
        h[i] = hh;
        l[i] = __float2half_rn(v - __half2float(hh));
    }
}

// ---------------------------------------------------------------------------
// 2-pass row softmax: single exp per element. Writes UNNORMALIZED p=exp(s-m)
// as fp16 for j in [i, S), zeros for [i_tile, i), and inv_l = 1/sum per row.
// Normalization is applied in the PV epilogue via rowscale.
// ---------------------------------------------------------------------------
__global__ __launch_bounds__(256)
void k_softmax(const float* __restrict__ Sc, __half* __restrict__ Ph,
               float* __restrict__ Linv)
{
    int i = blockIdx.x;
    int b = blockIdx.y;
    size_t off = ((size_t)b * Sq + i) * Sq;
    const float* row = Sc + off;
    __half* ph = Ph + off;
    int t = threadIdx.x;
    __shared__ float red[256];

    // pass 1: max over [i, S)
    float m = -3.402823466e38f;
    for (int j = i + t; j < Sq; j += 256) m = fmaxf(m, row[j]);
    red[t] = m; __syncthreads();
    for (int s = 128; s > 0; s >>= 1) {
        if (t < s) red[t] = fmaxf(red[t], red[t + s]);
        __syncthreads();
    }
    m = red[0];
    __syncthreads();

    // pass 2: exp once, write unnormalized p, accumulate sum
    float l = 0.f;
    for (int j = i + t; j < Sq; j += 256) {
        float e = __expf(row[j] - m);
        l += e;
        ph[j] = __float2half_rn(e);
    }
    // zero the masked prefix within this row's PV k-tile
    int i0 = i & ~(BM - 1);
    for (int j = i0 + t; j < i; j += 256) ph[j] = __float2half_rn(0.f);

    red[t] = l; __syncthreads();
    for (int s = 128; s > 0; s >>= 1) {
        if (t < s) red[t] += red[t + s];
        __syncthreads();
    }
    if (t == 0) Linv[(size_t)b * Sq + i] = 1.0f / red[0];
}

// ---------------------------------------------------------------------------
// Transpose v [S,H] -> vt [H,S] per batch, splitting to fp16 hi/lo.
// ---------------------------------------------------------------------------
__global__ __launch_bounds__(256)
void k_transpose_split(const float* __restrict__ V, __half* __restrict__ Th,
                       __half* __restrict__ Tl)
{
    __shared__ float t[32][33];
    int bz = blockIdx.z;
    const float* Vb = V + (size_t)bz * Sq * Hh;
    __half* Hb = Th + (size_t)bz * Sq * Hh;
    __half* Lb = Tl + (size_t)bz * Sq * Hh;
    int c0 = blockIdx.x * 32, r0 = blockIdx.y * 32;
    int tx = threadIdx.x & 31, ty = threadIdx.x >> 5;
    #pragma unroll
    for (int i = ty; i < 32; i += 8)
        t[i][tx] = Vb[(size_t)(r0 + i) * Hh + c0 + tx];
    __syncthreads();
    #pragma unroll
    for (int i = ty; i < 32; i += 8) {
        float v = t[tx][i];
        __half h = __float2half_rn(v);
        size_t o = (size_t)(c0 + i) * Sq + r0 + tx;
        Hb[o] = h;
        Lb[o] = __float2half_rn(v - __half2float(h));
    }
}

// ---------------------------------------------------------------------------
extern "C" void kernel_launch(void* const* d_in, const int* in_sizes, int n_in,
                              void* d_out, int out_size)
{
    (void)in_sizes; (void)n_in; (void)out_size;
    const float* x  = (const float*)d_in[0];
    const float* Wq = (const float*)d_in[1];
    const float* bq = (const float*)d_in[2];
    const float* Wk = (const float*)d_in[3];
    const float* bk = (const float*)d_in[4];
    const float* Wv = (const float*)d_in[5];
    const float* bv = (const float*)d_in[6];
    const float* Wm = (const float*)d_in[7];
    const float* bm = (const float*)d_in[8];
    float* out = (float*)d_out;

    __half *xh, *xl, *Wqh, *Wql, *Wkh, *Wkl, *Wvh, *Wvl, *Wmh, *Wml;
    __half *qh, *ql, *kh, *kl, *vth, *vtl, *ph, *ath, *atl;
    float *v, *sc, *linv;
    cudaGetSymbolAddress((void**)&xh,  g_xh);  cudaGetSymbolAddress((void**)&xl,  g_xl);
    cudaGetSymbolAddress((void**)&Wqh, g_Wqh); cudaGetSymbolAddress((void**)&Wql, g_Wql);
    cudaGetSymbolAddress((void**)&Wkh, g_Wkh); cudaGetSymbolAddress((void**)&Wkl, g_Wkl);
    cudaGetSymbolAddress((void**)&Wvh, g_Wvh); cudaGetSymbolAddress((void**)&Wvl, g_Wvl);
    cudaGetSymbolAddress((void**)&Wmh, g_Wmh); cudaGetSymbolAddress((void**)&Wml, g_Wml);
    cudaGetSymbolAddress((void**)&qh,  g_qh);  cudaGetSymbolAddress((void**)&ql,  g_ql);
    cudaGetSymbolAddress((void**)&kh,  g_kh);  cudaGetSymbolAddress((void**)&kl,  g_kl);
    cudaGetSymbolAddress((void**)&v,   g_v);
    cudaGetSymbolAddress((void**)&vth, g_vth); cudaGetSymbolAddress((void**)&vtl, g_vtl);
    cudaGetSymbolAddress((void**)&sc,  g_sc);
    cudaGetSymbolAddress((void**)&ph,  g_ph);
    cudaGetSymbolAddress((void**)&linv,g_linv);
    cudaGetSymbolAddress((void**)&ath, g_ath); cudaGetSymbolAddress((void**)&atl, g_atl);

    cudaFuncSetAttribute(k_hgemm, cudaFuncAttributeMaxDynamicSharedMemorySize, SMEM_SZ);

    dim3 blk(512);

    // Split inputs once.
    k_split<<<2048, 256>>>(x,  xh,  xl,  Bsz * Sq * Dd);
    k_split<<<256,  256>>>(Wq, Wqh, Wql, Dd * Hh);
    k_split<<<256,  256>>>(Wk, Wkh, Wkl, Dd * Hh);
    k_split<<<256,  256>>>(Wv, Wvh, Wvl, Dd * Hh);
    k_split<<<256,  256>>>(Wm, Wmh, Wml, Hh * Hh);

    dim3 gproj(Hh / BN, (Bsz * Sq) / BM, 1);      // 4 x 64

    // Projections (softmax 1/8 folded into q, incl. its bias).
    k_hgemm<<<gproj, blk, SMEM_SZ>>>(xh, xl, Wqh, Wql, bq, (float*)0, (float*)0, qh, ql,
                                     Bsz * Sq, Hh, Dd, 0.125f, 0.125f, 0, 0, 0, 0, 0);
    k_hgemm<<<gproj, blk, SMEM_SZ>>>(xh, xl, Wkh, Wkl, bk, (float*)0, (float*)0, kh, kl,
                                     Bsz * Sq, Hh, Dd, 1.0f, 1.0f, 0, 0, 0, 0, 0);
    k_hgemm<<<gproj, blk, SMEM_SZ>>>(xh, xl, Wvh, Wvl, bv, (float*)0, v, (__half*)0, (__half*)0,
                                     Bsz * Sq, Hh, Dd, 1.0f, 1.0f, 0, 0, 0, 0, 0);

    // Scores (fp32), upper-triangular blocks only (nb >= mb).
    k_hgemm<<<dim3(Sq / BN, Sq / BM, Bsz), blk, SMEM_SZ>>>(
        qh, ql, kh, kl, (const float*)0, (float*)0, sc, (__half*)0, (__half*)0,
        Sq, Sq, Hh, 1.0f, 0.0f,
        (long long)Sq * Hh, (long long)Sq * Hh, (long long)Sq * Sq, 1, 0);

    // 2-pass softmax -> unnormalized fp16 probs + inv rowsum.
    k_softmax<<<dim3(Sq, Bsz), 256>>>(sc, ph, linv);

    // vt = v^T (split), then attn = (P @ v) * inv_l, 2-term.
    // Default raster order runs mb=0 (heaviest: k range [0, S)) first.
    k_transpose_split<<<dim3(Hh / 32, Sq / 32, Bsz), 256>>>(v, vth, vtl);
    k_hgemm<<<dim3(Hh / BN, Sq / BM, Bsz), blk, SMEM_SZ>>>(
        ph, (__half*)0, vth, vtl, (const float*)0, linv, (float*)0, ath, atl,
        Sq, Hh, Sq, 1.0f, 0.0f,
        (long long)Sq * Sq, (long long)Sq * Hh, (long long)Sq * Hh, 0, 1);

    // out = 8 * attn @ Wm^T + bm  (NUM_HEADS folded into scale).
    k_hgemm<<<gproj, blk, SMEM_SZ>>>(ath, atl, Wmh, Wml, bm, (float*)0, out, (__half*)0, (__half*)0,
                                     Bsz * Sq, Hh, Dd, 8.0f, 1.0f, 0, 0, 0, 0, 0);
}

// round 13
// speedup vs baseline: 1.0862x; 1.0048x over previous
#include <cuda_runtime.h>
#include <cuda_fp16.h>
#include <cstdint>

// Problem constants (B=2, S=4096, D=H=512), softmax scale = sqrt(512/8)=8.
#define Bsz 2
#define Sq  4096
#define Dd  512
#define Hh  512

// Scratch (device globals: allocation inside kernel_launch is forbidden).
__device__ __half g_xh [(size_t)Bsz * Sq * Dd], g_xl [(size_t)Bsz * Sq * Dd];
__device__ __half g_Wqh[Dd * Hh], g_Wql[Dd * Hh];
__device__ __half g_Wkh[Dd * Hh], g_Wkl[Dd * Hh];
__device__ __half g_Wvh[Dd * Hh], g_Wvl[Dd * Hh];
__device__ __half g_Wmh[Hh * Hh], g_Wml[Hh * Hh];
__device__ __half g_qh [(size_t)Bsz * Sq * Hh], g_ql [(size_t)Bsz * Sq * Hh];
__device__ __half g_kh [(size_t)Bsz * Sq * Hh], g_kl [(size_t)Bsz * Sq * Hh];
__device__ float  g_v  [(size_t)Bsz * Sq * Hh];
__device__ __half g_vth[(size_t)Bsz * Sq * Hh], g_vtl[(size_t)Bsz * Sq * Hh];
__device__ float  g_sc [(size_t)Bsz * Sq * Sq];                    // 128 MB
__device__ __half g_ph [(size_t)Bsz * Sq * Sq];                    // 64 MB (unnormalized probs)
__device__ float  g_linv[(size_t)Bsz * Sq];                        // 1/rowsum
__device__ __half g_ath[(size_t)Bsz * Sq * Hh];                    // attn hi only (mix is 2-term)

// ---------------------------------------------------------------------------
// helpers
// ---------------------------------------------------------------------------
__device__ __forceinline__ uint32_t smem_u32(const void* p) {
    uint32_t a;
    asm("{ .reg .u64 t; cvta.to.shared.u64 t, %1; cvt.u32.u64 %0, t; }"
        : "=r"(a) : "l"(p));
    return a;
}
__device__ __forceinline__ void cp16(uint32_t smem, const void* g) {
    asm volatile("cp.async.cg.shared.global [%0], [%1], 16;"
                 :: "r"(smem), "l"(g) : "memory");
}
#define CP_COMMIT() asm volatile("cp.async.commit_group;" ::: "memory")
#define CP_WAIT(n)  asm volatile("cp.async.wait_group %0;" :: "n"(n) : "memory")

// ldmatrix: 4x m8n8 b16 matrices from shared (one address per lane).
#define LDSM4(r, addr)                                                        \
    asm volatile("ldmatrix.sync.aligned.m8n8.x4.shared.b16 "                  \
                 "{%0,%1,%2,%3}, [%4];"                                       \
                 : "=r"((r)[0]), "=r"((r)[1]), "=r"((r)[2]), "=r"((r)[3])     \
                 : "r"(addr))

// m16n8k16 fp16 mma, fp32 accum. row.col => both operands K-major (NT GEMM).
__device__ __forceinline__ void mma16(float* c, const uint32_t* a, const uint32_t* b) {
    asm volatile(
        "mma.sync.aligned.m16n8k16.row.col.f32.f16.f16.f32 "
        "{%0,%1,%2,%3}, {%4,%5,%6,%7}, {%8,%9}, {%0,%1,%2,%3};"
        : "+f"(c[0]), "+f"(c[1]), "+f"(c[2]), "+f"(c[3])
        : "r"(a[0]), "r"(a[1]), "r"(a[2]), "r"(a[3]), "r"(b[0]), "r"(b[1]));
}

// ---------------------------------------------------------------------------
// fp16x3 GEMM:  C = rowscale[r] * (scale * (A @ W^T) + bscale * bias)
// A as (Ah, Al) fp16 pair (Al null -> 2-term), W as (Wh, Wl). Outputs fp32 Cf
// and/or fp16 Ch (+ optional lo Cl). CTA tile 128x128, K-chunk 64, 512 thr =
// 16 warps (4Mx4N), warp tile 32x32, ldmatrix fragments, 3-stage cp.async.
// ---------------------------------------------------------------------------
#define BM 128
#define BN 128
#define KC 64
#define RS 36
#define PART (128 * RS)
#define PART4 (PART * 4)
#define STAGE (4 * PART)
#define STAGE4 (STAGE * 4)
#define NSTG 3
#define SMEM_SZ (NSTG * STAGE4)        // 216 KB

__global__ __launch_bounds__(512, 1)
void k_hgemm(const __half* __restrict__ Ah, const __half* __restrict__ Al,
             const __half* __restrict__ Wh, const __half* __restrict__ Wl,
             const float* __restrict__ bias, const float* __restrict__ rowscale,
             float* __restrict__ Cf, __half* __restrict__ Ch, __half* __restrict__ Cl,
             int M, int N, int K, float scale, float bscale,
             long long sA, long long sW, long long sC,
             int skip_lower, int diag_kstart)
{
    int nb = blockIdx.x, bz = blockIdx.z;
    int mb = blockIdx.y;
    if (skip_lower && nb < mb) return;          // block entirely masked (j < i)
    int hasAl = (Al != 0);
    Ah += (size_t)bz * sA;  if (hasAl) Al += (size_t)bz * sA;
    Wh += (size_t)bz * sW;  Wl += (size_t)bz * sW;
    if (Cf) Cf += (size_t)bz * sC;
    if (Ch) Ch += (size_t)bz * sC;
    if (Cl) Cl += (size_t)bz * sC;
    if (rowscale) rowscale += (size_t)bz * M;

    extern __shared__ uint32_t sm32[];
    uint32_t smb = smem_u32(sm32);

    int tid  = threadIdx.x;
    int warp = tid >> 5, lane = tid & 31;
    int wm = warp >> 2, wn = warp & 3;
    int g  = lane >> 2, q4 = lane & 3;
    int m0 = mb * BM, n0 = nb * BN;

    int kt0 = diag_kstart ? m0 : 0;
    int nch = (K - kt0) / KC;

    float acc[2][4][4];
    #pragma unroll
    for (int i = 0; i < 2; i++)
        #pragma unroll
        for (int j = 0; j < 4; j++)
            #pragma unroll
            for (int r = 0; r < 4; r++) acc[i][j][r] = 0.f;

    int lr  = tid >> 3;
    int seg = tid & 7;

    // per-lane ldmatrix byte offsets (within a stage); k-step adds ks*32B
    uint32_t a_off[2];
    #pragma unroll
    for (int tm = 0; tm < 2; tm++) {
        int row = wm * 32 + tm * 16 + (lane & 15);
        a_off[tm] = (uint32_t)(row * RS + (lane >> 4) * 4) * 4;
    }
    uint32_t b_off[2];
    #pragma unroll
    for (int p = 0; p < 2; p++) {
        int row = wn * 32 + p * 16 + (lane & 7) + ((lane >> 4) & 1) * 8;
        b_off[p] = (uint32_t)(row * RS + ((lane >> 3) & 1) * 4) * 4;
    }

    auto load_stage = [&](uint32_t sb, int kt) {
        #pragma unroll
        for (int j = 0; j < 2; j++) {
            int row = j * 64 + lr;
            uint32_t so = (uint32_t)(row * RS) * 4 + seg * 16;
            size_t ga = (size_t)(m0 + row) * K + kt + seg * 8;
            size_t gw = (size_t)(n0 + row) * K + kt + seg * 8;
            cp16(sb + so,              Ah + ga);
            if (hasAl) cp16(sb + PART4 + so, Al + ga);
            cp16(sb + 2 * PART4 + so,  Wh + gw);
            cp16(sb + 3 * PART4 + so,  Wl + gw);
        }
    };

    // prologue: prefetch up to 2 stages
    load_stage(smb, kt0);
    CP_COMMIT();
    if (nch > 1) { load_stage(smb + STAGE4, kt0 + KC); CP_COMMIT(); }

    for (int ic = 0; ic < nch; ic++) {
        if (ic + 2 < nch) {
            load_stage(smb + (uint32_t)((ic + 2) % NSTG) * STAGE4,
                       kt0 + (ic + 2) * KC);
            CP_COMMIT();
            CP_WAIT(2);
        } else if (ic + 1 < nch) {
            CP_WAIT(1);
        } else {
            CP_WAIT(0);
        }
        __syncthreads();

        uint32_t sbase = smb + (uint32_t)(ic % NSTG) * STAGE4;

        #pragma unroll
        for (int ks = 0; ks < 4; ks++) {
            uint32_t ko = (uint32_t)ks * 32;      // 8 u32 = 32 bytes per k16
            uint32_t ah[2][4], al[2][4];
            #pragma unroll
            for (int tm = 0; tm < 2; tm++) {
                LDSM4(ah[tm], sbase + a_off[tm] + ko);
                if (hasAl) LDSM4(al[tm], sbase + PART4 + a_off[tm] + ko);
            }
            uint32_t bh[2][4], bl[2][4];
            #pragma unroll
            for (int p = 0; p < 2; p++) {
                LDSM4(bh[p], sbase + 2 * PART4 + b_off[p] + ko);
                LDSM4(bl[p], sbase + 3 * PART4 + b_off[p] + ko);
            }
            #pragma unroll
            for (int tn = 0; tn < 4; tn++) {
                const uint32_t* bhp = &bh[tn >> 1][(tn & 1) * 2];
                const uint32_t* blp = &bl[tn >> 1][(tn & 1) * 2];
                #pragma unroll
                for (int tm = 0; tm < 2; tm++) {
                    mma16(acc[tm][tn], ah[tm], bhp);            // hi*hi
                    mma16(acc[tm][tn], ah[tm], blp);            // hi*lo
                    if (hasAl) mma16(acc[tm][tn], al[tm], bhp); // lo*hi
                }
            }
        }
        __syncthreads();
    }

    // ---- epilogue ----
    #pragma unroll
    for (int tm = 0; tm < 2; tm++) {
        int r = m0 + wm * 32 + tm * 16 + g;
        float rs0 = 1.f, rs1 = 1.f;
        if (rowscale) { rs0 = rowscale[r]; rs1 = rowscale[r + 8]; }
        #pragma unroll
        for (int tn = 0; tn < 4; tn++) {
            int cc = n0 + wn * 32 + tn * 8 + q4 * 2;
            float bv0 = 0.f, bv1 = 0.f;
            if (bias) {
                bv0 = bscale * __ldg(bias + cc);
                bv1 = bscale * __ldg(bias + cc + 1);
            }
            float v00 = (scale * acc[tm][tn][0] + bv0) * rs0;
            float v01 = (scale * acc[tm][tn][1] + bv1) * rs0;
            float v10 = (scale * acc[tm][tn][2] + bv0) * rs1;
            float v11 = (scale * acc[tm][tn][3] + bv1) * rs1;
            if (Cf) {
                *(float2*)(Cf + (size_t)r * N + cc)       = make_float2(v00, v01);
                *(float2*)(Cf + (size_t)(r + 8) * N + cc) = make_float2(v10, v11);
            }
            if (Ch) {
                __half h00 = __float2half_rn(v00), h01 = __float2half_rn(v01);
                __half h10 = __float2half_rn(v10), h11 = __float2half_rn(v11);
                *(__half2*)(Ch + (size_t)r * N + cc)       = __halves2half2(h00, h01);
                *(__half2*)(Ch + (size_t)(r + 8) * N + cc) = __halves2half2(h10, h11);
                if (Cl) {
                    *(__half2*)(Cl + (size_t)r * N + cc) = __halves2half2(
                        __float2half_rn(v00 - __half2float(h00)),
                        __float2half_rn(v01 - __half2float(h01)));
                    *(__half2*)(Cl + (size_t)(r + 8) * N + cc) = __halves2half2(
                        __float2half_rn(v10 - __half2float(h10)),
                        __float2half_rn(v11 - __half2float(h11)));
                }
            }
        }
    }
}

// ---------------------------------------------------------------------------
// Split fp32 -> fp16 hi/lo pair.
// ---------------------------------------------------------------------------
__global__ __launch_bounds__(256)
void k_split(const float* __restrict__ x, __half* __restrict__ h,
             __half* __restrict__ l, int n)
{
    for (int i = blockIdx.x * 256 + threadIdx.x; i < n; i += gridDim.x * 256) {
        float v = x[i];
        __half hh = __float2half_rn(v);
        h[i] = hh;
        l[i] = __float2half_rn(v - __half2float(hh));
    }
}

// ---------------------------------------------------------------------------
// Row softmax, single gmem read: pass 1 streams the row into smem while
// reducing the max; pass 2 computes exp from smem, writes unnormalized fp16
// probs for j in [i, S) (zeros for the in-tile prefix), and emits 1/rowsum.
// ---------------------------------------------------------------------------
__global__ __launch_bounds__(256)
void k_softmax(const float* __restrict__ Sc, __half* __restrict__ Ph,
               float* __restrict__ Linv)
{
    extern __shared__ float rowbuf[];     // Sq floats (16 KB)
    __shared__ float red[256];
    int i = blockIdx.x;
    int b = blockIdx.y;
    size_t off = ((size_t)b * Sq + i) * Sq;
    const float* row = Sc + off;
    __half* ph = Ph + off;
    int t = threadIdx.x;

    // pass 1: stream row -> smem, reduce max over [i, S)
    float m = -3.402823466e38f;
    for (int j = i + t; j < Sq; j += 256) {
        float s = row[j];
        rowbuf[j] = s;
        m = fmaxf(m, s);
    }
    red[t] = m; __syncthreads();
    for (int s = 128; s > 0; s >>= 1) {
        if (t < s) red[t] = fmaxf(red[t], red[t + s]);
        __syncthreads();
    }
    m = red[0];
    __syncthreads();

    // pass 2: exp from smem, write unnormalized p, accumulate sum
    float l = 0.f;
    for (int j = i + t; j < Sq; j += 256) {
        float e = __expf(rowbuf[j] - m);
        l += e;
        ph[j] = __float2half_rn(e);
    }
    // zero the masked prefix within this row's PV k-tile
    int i0 = i & ~(BM - 1);
    for (int j = i0 + t; j < i; j += 256) ph[j] = __float2half_rn(0.f);

    red[t] = l; __syncthreads();
    for (int s = 128; s > 0; s >>= 1) {
        if (t < s) red[t] += red[t + s];
        __syncthreads();
    }
    if (t == 0) Linv[(size_t)b * Sq + i] = 1.0f / red[0];
}

// ---------------------------------------------------------------------------
// Transpose v [S,H] -> vt [H,S] per batch, splitting to fp16 hi/lo.
// ---------------------------------------------------------------------------
__global__ __launch_bounds__(256)
void k_transpose_split(const float* __restrict__ V, __half* __restrict__ Th,
                       __half* __restrict__ Tl)
{
    __shared__ float t[32][33];
    int bz = blockIdx.z;
    const float* Vb = V + (size_t)bz * Sq * Hh;
    __half* Hb = Th + (size_t)bz * Sq * Hh;
    __half* Lb = Tl + (size_t)bz * Sq * Hh;
    int c0 = blockIdx.x * 32, r0 = blockIdx.y * 32;
    int tx = threadIdx.x & 31, ty = threadIdx.x >> 5;
    #pragma unroll
    for (int i = ty; i < 32; i += 8)
        t[i][tx] = Vb[(size_t)(r0 + i) * Hh + c0 + tx];
    __syncthreads();
    #pragma unroll
    for (int i = ty; i < 32; i += 8) {
        float v = t[tx][i];
        __half h = __float2half_rn(v);
        size_t o = (size_t)(c0 + i) * Sq + r0 + tx;
        Hb[o] = h;
        Lb[o] = __float2half_rn(v - __half2float(h));
    }
}

// ---------------------------------------------------------------------------
extern "C" void kernel_launch(void* const* d_in, const int* in_sizes, int n_in,
                              void* d_out, int out_size)
{
    (void)in_sizes; (void)n_in; (void)out_size;
    const float* x  = (const float*)d_in[0];
    const float* Wq = (const float*)d_in[1];
    const float* bq = (const float*)d_in[2];
    const float* Wk = (const float*)d_in[3];
    const float* bk = (const float*)d_in[4];
    const float* Wv = (const float*)d_in[5];
    const float* bv = (const float*)d_in[6];
    const float* Wm = (const float*)d_in[7];
    const float* bm = (const float*)d_in[8];
    float* out = (float*)d_out;

    __half *xh, *xl, *Wqh, *Wql, *Wkh, *Wkl, *Wvh, *Wvl, *Wmh, *Wml;
    __half *qh, *ql, *kh, *kl, *vth, *vtl, *ph, *ath;
    float *v, *sc, *linv;
    cudaGetSymbolAddress((void**)&xh,  g_xh);  cudaGetSymbolAddress((void**)&xl,  g_xl);
    cudaGetSymbolAddress((void**)&Wqh, g_Wqh); cudaGetSymbolAddress((void**)&Wql, g_Wql);
    cudaGetSymbolAddress((void**)&Wkh, g_Wkh); cudaGetSymbolAddress((void**)&Wkl, g_Wkl);
    cudaGetSymbolAddress((void**)&Wvh, g_Wvh); cudaGetSymbolAddress((void**)&Wvl, g_Wvl);
    cudaGetSymbolAddress((void**)&Wmh, g_Wmh); cudaGetSymbolAddress((void**)&Wml, g_Wml);
    cudaGetSymbolAddress((void**)&qh,  g_qh);  cudaGetSymbolAddress((void**)&ql,  g_ql);
    cudaGetSymbolAddress((void**)&kh,  g_kh);  cudaGetSymbolAddress((void**)&kl,  g_kl);
    cudaGetSymbolAddress((void**)&v,   g_v);
    cudaGetSymbolAddress((void**)&vth, g_vth); cudaGetSymbolAddress((void**)&vtl, g_vtl);
    cudaGetSymbolAddress((void**)&sc,  g_sc);
    cudaGetSymbolAddress((void**)&ph,  g_ph);
    cudaGetSymbolAddress((void**)&linv,g_linv);
    cudaGetSymbolAddress((void**)&ath, g_ath);

    cudaFuncSetAttribute(k_hgemm, cudaFuncAttributeMaxDynamicSharedMemorySize, SMEM_SZ);
    cudaFuncSetAttribute(k_softmax, cudaFuncAttributeMaxDynamicSharedMemorySize, Sq * 4);

    dim3 blk(512);

    // Split inputs once.
    k_split<<<2048, 256>>>(x,  xh,  xl,  Bsz * Sq * Dd);
    k_split<<<256,  256>>>(Wq, Wqh, Wql, Dd * Hh);
    k_split<<<256,  256>>>(Wk, Wkh, Wkl, Dd * Hh);
    k_split<<<256,  256>>>(Wv, Wvh, Wvl, Dd * Hh);
    k_split<<<256,  256>>>(Wm, Wmh, Wml, Hh * Hh);

    dim3 gproj(Hh / BN, (Bsz * Sq) / BM, 1);      // 4 x 64

    // Projections (softmax 1/8 folded into q, incl. its bias).
    k_hgemm<<<gproj, blk, SMEM_SZ>>>(xh, xl, Wqh, Wql, bq, (float*)0, (float*)0, qh, ql,
                                     Bsz * Sq, Hh, Dd, 0.125f, 0.125f, 0, 0, 0, 0, 0);
    k_hgemm<<<gproj, blk, SMEM_SZ>>>(xh, xl, Wkh, Wkl, bk, (float*)0, (float*)0, kh, kl,
                                     Bsz * Sq, Hh, Dd, 1.0f, 1.0f, 0, 0, 0, 0, 0);
    k_hgemm<<<gproj, blk, SMEM_SZ>>>(xh, xl, Wvh, Wvl, bv, (float*)0, v, (__half*)0, (__half*)0,
                                     Bsz * Sq, Hh, Dd, 1.0f, 1.0f, 0, 0, 0, 0, 0);

    // Scores (fp32), upper-triangular blocks only (nb >= mb).
    k_hgemm<<<dim3(Sq / BN, Sq / BM, Bsz), blk, SMEM_SZ>>>(
        qh, ql, kh, kl, (const float*)0, (float*)0, sc, (__half*)0, (__half*)0,
        Sq, Sq, Hh, 1.0f, 0.0f,
        (long long)Sq * Hh, (long long)Sq * Hh, (long long)Sq * Sq, 1, 0);

    // softmax -> unnormalized fp16 probs + inv rowsum (single gmem read).
    k_softmax<<<dim3(Sq, Bsz), 256, Sq * 4>>>(sc, ph, linv);

    // vt = v^T (split), then attn = (P @ v) * inv_l, 2-term; attn hi only.
    k_transpose_split<<<dim3(Hh / 32, Sq / 32, Bsz), 256>>>(v, vth, vtl);
    k_hgemm<<<dim3(Hh / BN, Sq / BM, Bsz), blk, SMEM_SZ>>>(
        ph, (__half*)0, vth, vtl, (const float*)0, linv, (float*)0, ath, (__half*)0,
        Sq, Hh, Sq, 1.0f, 0.0f,
        (long long)Sq * Sq, (long long)Sq * Hh, (long long)Sq * Hh, 0, 1);

    // out = 8 * attn @ Wm^T + bm  (2-term: attn hi x (Wm hi+lo)).
    k_hgemm<<<gproj, blk, SMEM_SZ>>>(ath, (__half*)0, Wmh, Wml, bm, (float*)0, out,
                                     (__half*)0, (__half*)0,
                                     Bsz * Sq, Hh, Dd, 8.0f, 1.0f, 0, 0, 0, 0, 0);
}

// round 14
// speedup vs baseline: 1.1433x; 1.0526x over previous
#include <cuda_runtime.h>
#include <cuda_fp16.h>
#include <cstdint>

// Problem constants (B=2, S=4096, D=H=512), softmax scale = sqrt(512/8)=8.
#define Bsz 2
#define Sq  4096
#define Dd  512
#define Hh  512
#define DW  (Dd * Hh)

// Scratch (device globals: allocation inside kernel_launch is forbidden).
__device__ __half g_xh  [(size_t)Bsz * Sq * Dd], g_xl [(size_t)Bsz * Sq * Dd];
__device__ __half g_Wqkh[2 * DW], g_Wqkl[2 * DW];      // (0.125*Wq | Wk), K-major
__device__ float  g_bqk [2 * Hh];                      // (0.125*bq | bk)
__device__ __half g_Wvh [DW], g_Wvl [DW];
__device__ __half g_Wmh [DW], g_Wml [DW];
__device__ __half g_qkh [(size_t)Bsz * Sq * 2 * Hh];   // q cols 0-511, k cols 512-1023
__device__ __half g_qkl [(size_t)Bsz * Sq * 2 * Hh];
__device__ float  g_v   [(size_t)Bsz * Sq * Hh];
__device__ __half g_vth [(size_t)Bsz * Sq * Hh], g_vtl[(size_t)Bsz * Sq * Hh];
__device__ float  g_sc  [(size_t)Bsz * Sq * Sq];       // 128 MB
__device__ __half g_ph  [(size_t)Bsz * Sq * Sq];       // 64 MB (unnormalized probs)
__device__ float  g_linv[(size_t)Bsz * Sq];            // 1/rowsum
__device__ __half g_ath [(size_t)Bsz * Sq * Hh];       // attn hi (mix is 2-term)

// ---------------------------------------------------------------------------
// helpers
// ---------------------------------------------------------------------------
__device__ __forceinline__ uint32_t smem_u32(const void* p) {
    uint32_t a;
    asm("{ .reg .u64 t; cvta.to.shared.u64 t, %1; cvt.u32.u64 %0, t; }"
        : "=r"(a) : "l"(p));
    return a;
}
__device__ __forceinline__ void cp16(uint32_t smem, const void* g) {
    asm volatile("cp.async.cg.shared.global [%0], [%1], 16;"
                 :: "r"(smem), "l"(g) : "memory");
}
#define CP_COMMIT() asm volatile("cp.async.commit_group;" ::: "memory")
#define CP_WAIT(n)  asm volatile("cp.async.wait_group %0;" :: "n"(n) : "memory")

#define LDSM4(r, addr)                                                        \
    asm volatile("ldmatrix.sync.aligned.m8n8.x4.shared.b16 "                  \
                 "{%0,%1,%2,%3}, [%4];"                                       \
                 : "=r"((r)[0]), "=r"((r)[1]), "=r"((r)[2]), "=r"((r)[3])     \
                 : "r"(addr))

// m16n8k16 fp16 mma, fp32 accum. row.col => both operands K-major (NT GEMM).
__device__ __forceinline__ void mma16(float* c, const uint32_t* a, const uint32_t* b) {
    asm volatile(
        "mma.sync.aligned.m16n8k16.row.col.f32.f16.f16.f32 "
        "{%0,%1,%2,%3}, {%4,%5,%6,%7}, {%8,%9}, {%0,%1,%2,%3};"
        : "+f"(c[0]), "+f"(c[1]), "+f"(c[2]), "+f"(c[3])
        : "r"(a[0]), "r"(a[1]), "r"(a[2]), "r"(a[3]), "r"(b[0]), "r"(b[1]));
}

// ---------------------------------------------------------------------------
// fp16x3 GEMM:  C = rowscale[r] * (scale * (A @ W^T) + bscale * bias)
// A as (Ah, Al) pair (Al null -> 2-term), W as (Wh, Wl). Outputs fp32 Cf
// and/or fp16 Ch. Explicit row strides lda/ldw/ldc (elements). CTA tile
// 128x128, KC=64, 512 thr = 16 warps (4Mx4N), ldmatrix fragments, 3-stage
// cp.async with ONE __syncthreads per mainloop iteration.
// ---------------------------------------------------------------------------
#define BM 128
#define BN 128
#define KC 64
#define RS 36
#define PART (128 * RS)
#define PART4 (PART * 4)
#define STAGE4 (4 * PART4)
#define NSTG 3
#define SMEM_SZ (NSTG * STAGE4)        // 216 KB

__global__ __launch_bounds__(512, 1)
void k_hgemm(const __half* __restrict__ Ah, const __half* __restrict__ Al,
             const __half* __restrict__ Wh, const __half* __restrict__ Wl,
             const float* __restrict__ bias, const float* __restrict__ rowscale,
             float* __restrict__ Cf, __half* __restrict__ Ch,
             int M, int N, int K, int lda, int ldw, int ldc,
             float scale, float bscale,
             long long sA, long long sW, long long sC,
             int skip_lower, int diag_kstart)
{
    int nb = blockIdx.x, bz = blockIdx.z;
    int mb = blockIdx.y;
    if (skip_lower && nb < mb) return;          // block entirely masked (j < i)
    int hasAl = (Al != 0);
    Ah += (size_t)bz * sA;  if (hasAl) Al += (size_t)bz * sA;
    Wh += (size_t)bz * sW;  Wl += (size_t)bz * sW;
    if (Cf) Cf += (size_t)bz * sC;
    if (Ch) Ch += (size_t)bz * sC;
    if (rowscale) rowscale += (size_t)bz * M;

    extern __shared__ uint32_t sm32[];
    uint32_t smb = smem_u32(sm32);

    int tid  = threadIdx.x;
    int warp = tid >> 5, lane = tid & 31;
    int wm = warp >> 2, wn = warp & 3;
    int g  = lane >> 2, q4 = lane & 3;
    int m0 = mb * BM, n0 = nb * BN;

    int kt0 = diag_kstart ? m0 : 0;
    int nch = (K - kt0) / KC;

    float acc[2][4][4];
    #pragma unroll
    for (int i = 0; i < 2; i++)
        #pragma unroll
        for (int j = 0; j < 4; j++)
            #pragma unroll
            for (int r = 0; r < 4; r++) acc[i][j][r] = 0.f;

    int lr  = tid >> 3;
    int seg = tid & 7;

    uint32_t a_off[2];
    #pragma unroll
    for (int tm = 0; tm < 2; tm++) {
        int row = wm * 32 + tm * 16 + (lane & 15);
        a_off[tm] = (uint32_t)(row * RS + (lane >> 4) * 4) * 4;
    }
    uint32_t b_off[2];
    #pragma unroll
    for (int p = 0; p < 2; p++) {
        int row = wn * 32 + p * 16 + (lane & 7) + ((lane >> 4) & 1) * 8;
        b_off[p] = (uint32_t)(row * RS + ((lane >> 3) & 1) * 4) * 4;
    }

    auto load_stage = [&](uint32_t sb, int kt) {
        #pragma unroll
        for (int j = 0; j < 2; j++) {
            int row = j * 64 + lr;
            uint32_t so = (uint32_t)(row * RS) * 4 + seg * 16;
            size_t ga = (size_t)(m0 + row) * lda + kt + seg * 8;
            size_t gw = (size_t)(n0 + row) * ldw + kt + seg * 8;
            cp16(sb + so,              Ah + ga);
            if (hasAl) cp16(sb + PART4 + so, Al + ga);
            cp16(sb + 2 * PART4 + so,  Wh + gw);
            cp16(sb + 3 * PART4 + so,  Wl + gw);
        }
    };

    // prologue: prefetch up to 2 stages
    load_stage(smb, kt0);
    CP_COMMIT();
    if (nch > 1) { load_stage(smb + STAGE4, kt0 + KC); CP_COMMIT(); }

    for (int ic = 0; ic < nch; ic++) {
        if (ic + 1 < nch) { CP_WAIT(1); } else { CP_WAIT(0); }
        __syncthreads();   // the ONLY barrier per iteration:
                           // - stage ic data visible to all warps
                           // - all warps done reading stage (ic-1)%3, which is
                           //   exactly the prefetch target (ic+2)%3 below
        if (ic + 2 < nch) {
            load_stage(smb + (uint32_t)((ic + 2) % NSTG) * STAGE4,
                       kt0 + (ic + 2) * KC);
            CP_COMMIT();
        }

        uint32_t sbase = smb + (uint32_t)(ic % NSTG) * STAGE4;

        #pragma unroll
        for (int ks = 0; ks < 4; ks++) {
            uint32_t ko = (uint32_t)ks * 32;      // 32 bytes per k16
            uint32_t ah[2][4], al[2][4];
            #pragma unroll
            for (int tm = 0; tm < 2; tm++) {
                LDSM4(ah[tm], sbase + a_off[tm] + ko);
                if (hasAl) LDSM4(al[tm], sbase + PART4 + a_off[tm] + ko);
            }
            uint32_t bh[2][4], bl[2][4];
            #pragma unroll
            for (int p = 0; p < 2; p++) {
                LDSM4(bh[p], sbase + 2 * PART4 + b_off[p] + ko);
                LDSM4(bl[p], sbase + 3 * PART4 + b_off[p] + ko);
            }
            #pragma unroll
            for (int tn = 0; tn < 4; tn++) {
                const uint32_t* bhp = &bh[tn >> 1][(tn & 1) * 2];
                const uint32_t* blp = &bl[tn >> 1][(tn & 1) * 2];
                #pragma unroll
                for (int tm = 0; tm < 2; tm++) {
                    mma16(acc[tm][tn], ah[tm], bhp);            // hi*hi
                    mma16(acc[tm][tn], ah[tm], blp);            // hi*lo
                    if (hasAl) mma16(acc[tm][tn], al[tm], bhp); // lo*hi
                }
            }
        }
    }

    // ---- epilogue ----
    #pragma unroll
    for (int tm = 0; tm < 2; tm++) {
        int r = m0 + wm * 32 + tm * 16 + g;
        float rs0 = 1.f, rs1 = 1.f;
        if (rowscale) { rs0 = rowscale[r]; rs1 = rowscale[r + 8]; }
        #pragma unroll
        for (int tn = 0; tn < 4; tn++) {
            int cc = n0 + wn * 32 + tn * 8 + q4 * 2;
            float bv0 = 0.f, bv1 = 0.f;
            if (bias) {
                bv0 = bscale * __ldg(bias + cc);
                bv1 = bscale * __ldg(bias + cc + 1);
            }
            float v00 = (scale * acc[tm][tn][0] + bv0) * rs0;
            float v01 = (scale * acc[tm][tn][1] + bv1) * rs0;
            float v10 = (scale * acc[tm][tn][2] + bv0) * rs1;
            float v11 = (scale * acc[tm][tn][3] + bv1) * rs1;
            if (Cf) {
                *(float2*)(Cf + (size_t)r * ldc + cc)       = make_float2(v00, v01);
                *(float2*)(Cf + (size_t)(r + 8) * ldc + cc) = make_float2(v10, v11);
            }
            if (Ch) {
                __half h00 = __float2half_rn(v00), h01 = __float2half_rn(v01);
                __half h10 = __float2half_rn(v10), h11 = __float2half_rn(v11);
                *(__half2*)(Ch + (size_t)r * ldc + cc)       = __halves2half2(h00, h01);
                *(__half2*)(Ch + (size_t)(r + 8) * ldc + cc) = __halves2half2(h10, h11);
            }
        }
    }
}

// Variant epilogue pair-writer for q/k (hi AND lo needed by the score GEMM).
// Implemented as a second kernel to keep k_hgemm lean: identical mainloop,
// but writes Ch and Cl. Used for projqk only.
__global__ __launch_bounds__(512, 1)
void k_hgemm_hl(const __half* __restrict__ Ah, const __half* __restrict__ Al,
                const __half* __restrict__ Wh, const __half* __restrict__ Wl,
                const float* __restrict__ bias,
                __half* __restrict__ Ch, __half* __restrict__ Cl,
                int M, int N, int K, int lda, int ldw, int ldc)
{
    int nb = blockIdx.x, mb = blockIdx.y;
    extern __shared__ uint32_t sm32[];
    uint32_t smb = smem_u32(sm32);

    int tid  = threadIdx.x;
    int warp = tid >> 5, lane = tid & 31;
    int wm = warp >> 2, wn = warp & 3;
    int g  = lane >> 2, q4 = lane & 3;
    int m0 = mb * BM, n0 = nb * BN;
    int nch = K / KC;

    float acc[2][4][4];
    #pragma unroll
    for (int i = 0; i < 2; i++)
        #pragma unroll
        for (int j = 0; j < 4; j++)
            #pragma unroll
            for (int r = 0; r < 4; r++) acc[i][j][r] = 0.f;

    int lr  = tid >> 3;
    int seg = tid & 7;

    uint32_t a_off[2];
    #pragma unroll
    for (int tm = 0; tm < 2; tm++) {
        int row = wm * 32 + tm * 16 + (lane & 15);
        a_off[tm] = (uint32_t)(row * RS + (lane >> 4) * 4) * 4;
    }
    uint32_t b_off[2];
    #pragma unroll
    for (int p = 0; p < 2; p++) {
        int row = wn * 32 + p * 16 + (lane & 7) + ((lane >> 4) & 1) * 8;
        b_off[p] = (uint32_t)(row * RS + ((lane >> 3) & 1) * 4) * 4;
    }

    auto load_stage = [&](uint32_t sb, int kt) {
        #pragma unroll
        for (int j = 0; j < 2; j++) {
            int row = j * 64 + lr;
            uint32_t so = (uint32_t)(row * RS) * 4 + seg * 16;
            size_t ga = (size_t)(m0 + row) * lda + kt + seg * 8;
            size_t gw = (size_t)(n0 + row) * ldw + kt + seg * 8;
            cp16(sb + so,              Ah + ga);
            cp16(sb + PART4 + so,      Al + ga);
            cp16(sb + 2 * PART4 + so,  Wh + gw);
            cp16(sb + 3 * PART4 + so,  Wl + gw);
        }
    };

    load_stage(smb, 0);
    CP_COMMIT();
    if (nch > 1) { load_stage(smb + STAGE4, KC); CP_COMMIT(); }

    for (int ic = 0; ic < nch; ic++) {
        if (ic + 1 < nch) { CP_WAIT(1); } else { CP_WAIT(0); }
        __syncthreads();
        if (ic + 2 < nch) {
            load_stage(smb + (uint32_t)((ic + 2) % NSTG) * STAGE4, (ic + 2) * KC);
            CP_COMMIT();
        }
        uint32_t sbase = smb + (uint32_t)(ic % NSTG) * STAGE4;
        #pragma unroll
        for (int ks = 0; ks < 4; ks++) {
            uint32_t ko = (uint32_t)ks * 32;
            uint32_t ah[2][4], al[2][4];
            #pragma unroll
            for (int tm = 0; tm < 2; tm++) {
                LDSM4(ah[tm], sbase + a_off[tm] + ko);
                LDSM4(al[tm], sbase + PART4 + a_off[tm] + ko);
            }
            uint32_t bh[2][4], bl[2][4];
            #pragma unroll
            for (int p = 0; p < 2; p++) {
                LDSM4(bh[p], sbase + 2 * PART4 + b_off[p] + ko);
                LDSM4(bl[p], sbase + 3 * PART4 + b_off[p] + ko);
            }
            #pragma unroll
            for (int tn = 0; tn < 4; tn++) {
                const uint32_t* bhp = &bh[tn >> 1][(tn & 1) * 2];
                const uint32_t* blp = &bl[tn >> 1][(tn & 1) * 2];
                #pragma unroll
                for (int tm = 0; tm < 2; tm++) {
                    mma16(acc[tm][tn], ah[tm], bhp);
                    mma16(acc[tm][tn], ah[tm], blp);
                    mma16(acc[tm][tn], al[tm], bhp);
                }
            }
        }
    }

    #pragma unroll
    for (int tm = 0; tm < 2; tm++) {
        int r = m0 + wm * 32 + tm * 16 + g;
        #pragma unroll
        for (int tn = 0; tn < 4; tn++) {
            int cc = n0 + wn * 32 + tn * 8 + q4 * 2;
            float bv0 = __ldg(bias + cc);
            float bv1 = __ldg(bias + cc + 1);
            float v00 = acc[tm][tn][0] + bv0;
            float v01 = acc[tm][tn][1] + bv1;
            float v10 = acc[tm][tn][2] + bv0;
            float v11 = acc[tm][tn][3] + bv1;
            __half h00 = __float2half_rn(v00), h01 = __float2half_rn(v01);
            __half h10 = __float2half_rn(v10), h11 = __float2half_rn(v11);
            *(__half2*)(Ch + (size_t)r * ldc + cc)       = __halves2half2(h00, h01);
            *(__half2*)(Ch + (size_t)(r + 8) * ldc + cc) = __halves2half2(h10, h11);
            *(__half2*)(Cl + (size_t)r * ldc + cc) = __halves2half2(
                __float2half_rn(v00 - __half2float(h00)),
                __float2half_rn(v01 - __half2float(h01)));
            *(__half2*)(Cl + (size_t)(r + 8) * ldc + cc) = __halves2half2(
                __float2half_rn(v10 - __half2float(h10)),
                __float2half_rn(v11 - __half2float(h11)));
        }
    }
}

// ---------------------------------------------------------------------------
// Fused prep: split x; build (0.125*Wq | Wk) and (0.125*bq | bk); split Wv, Wm.
// ---------------------------------------------------------------------------
__global__ __launch_bounds__(256)
void k_prep(const float* __restrict__ x,
            const float* __restrict__ Wq, const float* __restrict__ bq,
            const float* __restrict__ Wk, const float* __restrict__ bk,
            const float* __restrict__ Wv, const float* __restrict__ Wm)
{
    int stride = gridDim.x * 256;
    int gid = blockIdx.x * 256 + threadIdx.x;

    for (int i = gid; i < Bsz * Sq * Dd; i += stride) {
        float v = x[i];
        __half h = __float2half_rn(v);
        g_xh[i] = h;
        g_xl[i] = __float2half_rn(v - __half2float(h));
    }
    for (int i = gid; i < DW; i += stride) {
        float wq = 0.125f * Wq[i];               // exact (power of 2)
        __half h = __float2half_rn(wq);
        g_Wqkh[i] = h;
        g_Wqkl[i] = __float2half_rn(wq - __half2float(h));
        float wk = Wk[i];
        h = __float2half_rn(wk);
        g_Wqkh[DW + i] = h;
        g_Wqkl[DW + i] = __float2half_rn(wk - __half2float(h));
        float wv = Wv[i];
        h = __float2half_rn(wv);
        g_Wvh[i] = h;
        g_Wvl[i] = __float2half_rn(wv - __half2float(h));
        float wm = Wm[i];
        h = __float2half_rn(wm);
        g_Wmh[i] = h;
        g_Wml[i] = __float2half_rn(wm - __half2float(h));
    }
    for (int i = gid; i < Hh; i += stride) {
        g_bqk[i]      = 0.125f * bq[i];
        g_bqk[Hh + i] = bk[i];
    }
}

// ---------------------------------------------------------------------------
// Row softmax, single gmem read (row buffered in smem), unnormalized fp16
// probs for j in [i, S) (zeros for the in-tile prefix) + 1/rowsum.
// ---------------------------------------------------------------------------
__global__ __launch_bounds__(256)
void k_softmax(const float* __restrict__ Sc, __half* __restrict__ Ph,
               float* __restrict__ Linv)
{
    extern __shared__ float rowbuf[];
    __shared__ float red[256];
    int i = blockIdx.x;
    int b = blockIdx.y;
    size_t off = ((size_t)b * Sq + i) * Sq;
    const float* row = Sc + off;
    __half* ph = Ph + off;
    int t = threadIdx.x;

    float m = -3.402823466e38f;
    for (int j = i + t; j < Sq; j += 256) {
        float s = row[j];
        rowbuf[j] = s;
        m = fmaxf(m, s);
    }
    red[t] = m; __syncthreads();
    for (int s = 128; s > 0; s >>= 1) {
        if (t < s) red[t] = fmaxf(red[t], red[t + s]);
        __syncthreads();
    }
    m = red[0];
    __syncthreads();

    float l = 0.f;
    for (int j = i + t; j < Sq; j += 256) {
        float e = __expf(rowbuf[j] - m);
        l += e;
        ph[j] = __float2half_rn(e);
    }
    int i0 = i & ~(BM - 1);
    for (int j = i0 + t; j < i; j += 256) ph[j] = __float2half_rn(0.f);

    red[t] = l; __syncthreads();
    for (int s = 128; s > 0; s >>= 1) {
        if (t < s) red[t] += red[t + s];
        __syncthreads();
    }
    if (t == 0) Linv[(size_t)b * Sq + i] = 1.0f / red[0];
}

// ---------------------------------------------------------------------------
// Transpose v [S,H] -> vt [H,S] per batch, splitting to fp16 hi/lo.
// ---------------------------------------------------------------------------
__global__ __launch_bounds__(256)
void k_transpose_split(const float* __restrict__ V, __half* __restrict__ Th,
                       __half* __restrict__ Tl)
{
    __shared__ float t[32][33];
    int bz = blockIdx.z;
    const float* Vb = V + (size_t)bz * Sq * Hh;
    __half* Hb = Th + (size_t)bz * Sq * Hh;
    __half* Lb = Tl + (size_t)bz * Sq * Hh;
    int c0 = blockIdx.x * 32, r0 = blockIdx.y * 32;
    int tx = threadIdx.x & 31, ty = threadIdx.x >> 5;
    #pragma unroll
    for (int i = ty; i < 32; i += 8)
        t[i][tx] = Vb[(size_t)(r0 + i) * Hh + c0 + tx];
    __syncthreads();
    #pragma unroll
    for (int i = ty; i < 32; i += 8) {
        float v = t[tx][i];
        __half h = __float2half_rn(v);
        size_t o = (size_t)(c0 + i) * Sq + r0 + tx;
        Hb[o] = h;
        Lb[o] = __float2half_rn(v - __half2float(h));
    }
}

// ---------------------------------------------------------------------------
extern "C" void kernel_launch(void* const* d_in, const int* in_sizes, int n_in,
                              void* d_out, int out_size)
{
    (void)in_sizes; (void)n_in; (void)out_size;
    const float* x  = (const float*)d_in[0];
    const float* Wq = (const float*)d_in[1];
    const float* bq = (const float*)d_in[2];
    const float* Wk = (const float*)d_in[3];
    const float* bk = (const float*)d_in[4];
    const float* Wv = (const float*)d_in[5];
    const float* bv = (const float*)d_in[6];
    const float* Wm = (const float*)d_in[7];
    const float* bm = (const float*)d_in[8];
    float* out = (float*)d_out;

    __half *xh, *xl, *Wqkh, *Wqkl, *Wvh, *Wvl, *Wmh, *Wml;
    __half *qkh, *qkl, *vth, *vtl, *ph, *ath;
    float *v, *sc, *linv, *bqk;
    cudaGetSymbolAddress((void**)&xh,   g_xh);   cudaGetSymbolAddress((void**)&xl,   g_xl);
    cudaGetSymbolAddress((void**)&Wqkh, g_Wqkh); cudaGetSymbolAddress((void**)&Wqkl, g_Wqkl);
    cudaGetSymbolAddress((void**)&bqk,  g_bqk);
    cudaGetSymbolAddress((void**)&Wvh,  g_Wvh);  cudaGetSymbolAddress((void**)&Wvl,  g_Wvl);
    cudaGetSymbolAddress((void**)&Wmh,  g_Wmh);  cudaGetSymbolAddress((void**)&Wml,  g_Wml);
    cudaGetSymbolAddress((void**)&qkh,  g_qkh);  cudaGetSymbolAddress((void**)&qkl,  g_qkl);
    cudaGetSymbolAddress((void**)&v,    g_v);
    cudaGetSymbolAddress((void**)&vth,  g_vth);  cudaGetSymbolAddress((void**)&vtl,  g_vtl);
    cudaGetSymbolAddress((void**)&sc,   g_sc);
    cudaGetSymbolAddress((void**)&ph,   g_ph);
    cudaGetSymbolAddress((void**)&linv, g_linv);
    cudaGetSymbolAddress((void**)&ath,  g_ath);

    cudaFuncSetAttribute(k_hgemm,    cudaFuncAttributeMaxDynamicSharedMemorySize, SMEM_SZ);
    cudaFuncSetAttribute(k_hgemm_hl, cudaFuncAttributeMaxDynamicSharedMemorySize, SMEM_SZ);
    cudaFuncSetAttribute(k_softmax,  cudaFuncAttributeMaxDynamicSharedMemorySize, Sq * 4);

    dim3 blk(512);

    // Fused prep: split x / weights, build concat qk weight + bias.
    k_prep<<<2048, 256>>>(x, Wq, bq, Wk, bk, Wv, Wm);

    // q|k projection (one GEMM, N=1024; 0.125 folded into Wq/bq exactly).
    k_hgemm_hl<<<dim3(2 * Hh / BN, (Bsz * Sq) / BM, 1), blk, SMEM_SZ>>>(
        xh, xl, Wqkh, Wqkl, bqk, qkh, qkl,
        Bsz * Sq, 2 * Hh, Dd, Dd, Dd, 2 * Hh);

    // v projection (fp32 out).
    k_hgemm<<<dim3(Hh / BN, (Bsz * Sq) / BM, 1), blk, SMEM_SZ>>>(
        xh, xl, Wvh, Wvl, bv, (float*)0, v, (__half*)0,
        Bsz * Sq, Hh, Dd, Dd, Dd, Hh, 1.0f, 1.0f, 0, 0, 0, 0, 0);

    // Scores (fp32), upper-triangular blocks only: q/k read from qk buffer.
    k_hgemm<<<dim3(Sq / BN, Sq / BM, Bsz), blk, SMEM_SZ>>>(
        qkh, qkl, qkh + Hh, qkl + Hh, (const float*)0, (float*)0, sc, (__half*)0,
        Sq, Sq, Hh, 2 * Hh, 2 * Hh, Sq, 1.0f, 0.0f,
        (long long)Sq * 2 * Hh, (long long)Sq * 2 * Hh, (long long)Sq * Sq, 1, 0);

    // softmax -> unnormalized fp16 probs + inv rowsum.
    k_softmax<<<dim3(Sq, Bsz), 256, Sq * 4>>>(sc, ph, linv);

    // vt = v^T (split), then attn = (P @ v) * inv_l, 2-term; attn hi only.
    k_transpose_split<<<dim3(Hh / 32, Sq / 32, Bsz), 256>>>(v, vth, vtl);
    k_hgemm<<<dim3(Hh / BN, Sq / BM, Bsz), blk, SMEM_SZ>>>(
        ph, (__half*)0, vth, vtl, (const float*)0, linv, (float*)0, ath,
        Sq, Hh, Sq, Sq, Sq, Hh, 1.0f, 0.0f,
        (long long)Sq * Sq, (long long)Sq * Hh, (long long)Sq * Hh, 0, 1);

    // out = 8 * attn @ Wm^T + bm  (2-term).
    k_hgemm<<<dim3(Hh / BN, (Bsz * Sq) / BM, 1), blk, SMEM_SZ>>>(
        ath, (__half*)0, Wmh, Wml, bm, (float*)0, out, (__half*)0,
        Bsz * Sq, Hh, Dd, Dd, Dd, Hh, 8.0f, 1.0f, 0, 0, 0, 0, 0);
}

// round 15
// speedup vs baseline: 1.2975x; 1.1348x over previous
#include <cuda_runtime.h>
#include <cuda_fp16.h>
#include <cstdint>

// Problem constants (B=2, S=4096, D=H=512), softmax scale = sqrt(512/8)=8.
#define Bsz 2
#define Sq  4096
#define Dd  512
#define Hh  512
#define DW  (Dd * Hh)

// Scratch (device globals: allocation inside kernel_launch is forbidden).
__device__ __half g_xh  [(size_t)Bsz * Sq * Dd], g_xl [(size_t)Bsz * Sq * Dd];
__device__ __half g_Wqkh[2 * DW], g_Wqkl[2 * DW];      // (0.125*Wq | Wk), K-major
__device__ float  g_bqk [2 * Hh];                      // (0.125*bq | bk)
__device__ __half g_Wvh [DW], g_Wvl [DW];
__device__ __half g_Wmh [DW], g_Wml [DW];
__device__ __half g_qkh [(size_t)Bsz * Sq * 2 * Hh];   // q cols 0-511, k cols 512-1023
__device__ __half g_qkl [(size_t)Bsz * Sq * 2 * Hh];
__device__ float  g_v   [(size_t)Bsz * Sq * Hh];
__device__ __half g_vth [(size_t)Bsz * Sq * Hh], g_vtl[(size_t)Bsz * Sq * Hh];
__device__ float  g_sc  [(size_t)Bsz * Sq * Sq];       // 128 MB
__device__ __half g_ph  [(size_t)Bsz * Sq * Sq];       // 64 MB (unnormalized probs)
__device__ float  g_linv[(size_t)Bsz * Sq];            // 1/rowsum
__device__ __half g_ath [(size_t)Bsz * Sq * Hh];       // attn hi (mix is 2-term)

// ---------------------------------------------------------------------------
// helpers
// ---------------------------------------------------------------------------
__device__ __forceinline__ uint32_t smem_u32(const void* p) {
    uint32_t a;
    asm("{ .reg .u64 t; cvta.to.shared.u64 t, %1; cvt.u32.u64 %0, t; }"
        : "=r"(a) : "l"(p));
    return a;
}
__device__ __forceinline__ void cp16(uint32_t smem, const void* g) {
    asm volatile("cp.async.cg.shared.global [%0], [%1], 16;"
                 :: "r"(smem), "l"(g) : "memory");
}
#define CP_COMMIT() asm volatile("cp.async.commit_group;" ::: "memory")
#define CP_WAIT(n)  asm volatile("cp.async.wait_group %0;" :: "n"(n) : "memory")

#define LDSM4(r, addr)                                                        \
    asm volatile("ldmatrix.sync.aligned.m8n8.x4.shared.b16 "                  \
                 "{%0,%1,%2,%3}, [%4];"                                       \
                 : "=r"((r)[0]), "=r"((r)[1]), "=r"((r)[2]), "=r"((r)[3])     \
                 : "r"(addr))

// m16n8k16 fp16 mma, fp32 accum. row.col => both operands K-major (NT GEMM).
__device__ __forceinline__ void mma16(float* c, const uint32_t* a, const uint32_t* b) {
    asm volatile(
        "mma.sync.aligned.m16n8k16.row.col.f32.f16.f16.f32 "
        "{%0,%1,%2,%3}, {%4,%5,%6,%7}, {%8,%9}, {%0,%1,%2,%3};"
        : "+f"(c[0]), "+f"(c[1]), "+f"(c[2]), "+f"(c[3])
        : "r"(a[0]), "r"(a[1]), "r"(a[2]), "r"(a[3]), "r"(b[0]), "r"(b[1]));
}

// ---------------------------------------------------------------------------
// fp16x3 GEMM:  C = rowscale[r] * (scale * (A @ W^T) + bscale * bias)
// A as (Ah, Al) pair (Al null -> 2-term), W as (Wh, Wl). Outputs fp32 Cf
// and/or fp16 Ch. Explicit row strides lda/ldw/ldc. CTA tile 128x128, KC=64,
// 512 thr = 16 warps (4Mx4N), ldmatrix fragments, 3-stage cp.async, ONE
// __syncthreads per iteration. MMA issue is TERM-MAJOR: all 8 independent
// accumulator tiles between dependent reuses (covers HMMA latency).
// ---------------------------------------------------------------------------
#define BM 128
#define BN 128
#define KC 64
#define RS 36
#define PART (128 * RS)
#define PART4 (PART * 4)
#define STAGE4 (4 * PART4)
#define NSTG 3
#define SMEM_SZ (NSTG * STAGE4)        // 216 KB

__global__ __launch_bounds__(512, 1)
void k_hgemm(const __half* __restrict__ Ah, const __half* __restrict__ Al,
             const __half* __restrict__ Wh, const __half* __restrict__ Wl,
             const float* __restrict__ bias, const float* __restrict__ rowscale,
             float* __restrict__ Cf, __half* __restrict__ Ch,
             int M, int N, int K, int lda, int ldw, int ldc,
             float scale, float bscale,
             long long sA, long long sW, long long sC,
             int skip_lower, int diag_kstart)
{
    int nb = blockIdx.x, bz = blockIdx.z;
    int mb = blockIdx.y;
    if (skip_lower && nb < mb) return;          // block entirely masked (j < i)
    int hasAl = (Al != 0);
    Ah += (size_t)bz * sA;  if (hasAl) Al += (size_t)bz * sA;
    Wh += (size_t)bz * sW;  Wl += (size_t)bz * sW;
    if (Cf) Cf += (size_t)bz * sC;
    if (Ch) Ch += (size_t)bz * sC;
    if (rowscale) rowscale += (size_t)bz * M;

    extern __shared__ uint32_t sm32[];
    uint32_t smb = smem_u32(sm32);

    int tid  = threadIdx.x;
    int warp = tid >> 5, lane = tid & 31;
    int wm = warp >> 2, wn = warp & 3;
    int g  = lane >> 2, q4 = lane & 3;
    int m0 = mb * BM, n0 = nb * BN;

    int kt0 = diag_kstart ? m0 : 0;
    int nch = (K - kt0) / KC;

    float acc[2][4][4];
    #pragma unroll
    for (int i = 0; i < 2; i++)
        #pragma unroll
        for (int j = 0; j < 4; j++)
            #pragma unroll
            for (int r = 0; r < 4; r++) acc[i][j][r] = 0.f;

    int lr  = tid >> 3;
    int seg = tid & 7;

    uint32_t a_off[2];
    #pragma unroll
    for (int tm = 0; tm < 2; tm++) {
        int row = wm * 32 + tm * 16 + (lane & 15);
        a_off[tm] = (uint32_t)(row * RS + (lane >> 4) * 4) * 4;
    }
    uint32_t b_off[2];
    #pragma unroll
    for (int p = 0; p < 2; p++) {
        int row = wn * 32 + p * 16 + (lane & 7) + ((lane >> 4) & 1) * 8;
        b_off[p] = (uint32_t)(row * RS + ((lane >> 3) & 1) * 4) * 4;
    }

    auto load_stage = [&](uint32_t sb, int kt) {
        #pragma unroll
        for (int j = 0; j < 2; j++) {
            int row = j * 64 + lr;
            uint32_t so = (uint32_t)(row * RS) * 4 + seg * 16;
            size_t ga = (size_t)(m0 + row) * lda + kt + seg * 8;
            size_t gw = (size_t)(n0 + row) * ldw + kt + seg * 8;
            cp16(sb + so,              Ah + ga);
            if (hasAl) cp16(sb + PART4 + so, Al + ga);
            cp16(sb + 2 * PART4 + so,  Wh + gw);
            cp16(sb + 3 * PART4 + so,  Wl + gw);
        }
    };

    load_stage(smb, kt0);
    CP_COMMIT();
    if (nch > 1) { load_stage(smb + STAGE4, kt0 + KC); CP_COMMIT(); }

    for (int ic = 0; ic < nch; ic++) {
        if (ic + 1 < nch) { CP_WAIT(1); } else { CP_WAIT(0); }
        __syncthreads();   // single barrier: stage ic visible; stage (ic+2)%3
                           // (== (ic-1)%3) is reusable by the prefetch below
        if (ic + 2 < nch) {
            load_stage(smb + (uint32_t)((ic + 2) % NSTG) * STAGE4,
                       kt0 + (ic + 2) * KC);
            CP_COMMIT();
        }

        uint32_t sbase = smb + (uint32_t)(ic % NSTG) * STAGE4;

        #pragma unroll
        for (int ks = 0; ks < 4; ks++) {
            uint32_t ko = (uint32_t)ks * 32;      // 32 bytes per k16
            uint32_t ah[2][4], al[2][4];
            #pragma unroll
            for (int tm = 0; tm < 2; tm++) {
                LDSM4(ah[tm], sbase + a_off[tm] + ko);
                if (hasAl) LDSM4(al[tm], sbase + PART4 + a_off[tm] + ko);
            }
            uint32_t bh[2][4], bl[2][4];
            #pragma unroll
            for (int p = 0; p < 2; p++) {
                LDSM4(bh[p], sbase + 2 * PART4 + b_off[p] + ko);
                LDSM4(bl[p], sbase + 3 * PART4 + b_off[p] + ko);
            }
            // term-major issue: 8 independent MMAs between accumulator reuses
            #pragma unroll
            for (int tn = 0; tn < 4; tn++) {
                const uint32_t* bhp = &bh[tn >> 1][(tn & 1) * 2];
                #pragma unroll
                for (int tm = 0; tm < 2; tm++)
                    mma16(acc[tm][tn], ah[tm], bhp);           // hi*hi
            }
            #pragma unroll
            for (int tn = 0; tn < 4; tn++) {
                const uint32_t* blp = &bl[tn >> 1][(tn & 1) * 2];
                #pragma unroll
                for (int tm = 0; tm < 2; tm++)
                    mma16(acc[tm][tn], ah[tm], blp);           // hi*lo
            }
            if (hasAl) {
                #pragma unroll
                for (int tn = 0; tn < 4; tn++) {
                    const uint32_t* bhp = &bh[tn >> 1][(tn & 1) * 2];
                    #pragma unroll
                    for (int tm = 0; tm < 2; tm++)
                        mma16(acc[tm][tn], al[tm], bhp);       // lo*hi
                }
            }
        }
    }

    // ---- epilogue ----
    #pragma unroll
    for (int tm = 0; tm < 2; tm++) {
        int r = m0 + wm * 32 + tm * 16 + g;
        float rs0 = 1.f, rs1 = 1.f;
        if (rowscale) { rs0 = rowscale[r]; rs1 = rowscale[r + 8]; }
        #pragma unroll
        for (int tn = 0; tn < 4; tn++) {
            int cc = n0 + wn * 32 + tn * 8 + q4 * 2;
            float bv0 = 0.f, bv1 = 0.f;
            if (bias) {
                bv0 = bscale * __ldg(bias + cc);
                bv1 = bscale * __ldg(bias + cc + 1);
            }
            float v00 = (scale * acc[tm][tn][0] + bv0) * rs0;
            float v01 = (scale * acc[tm][tn][1] + bv1) * rs0;
            float v10 = (scale * acc[tm][tn][2] + bv0) * rs1;
            float v11 = (scale * acc[tm][tn][3] + bv1) * rs1;
            if (Cf) {
                *(float2*)(Cf + (size_t)r * ldc + cc)       = make_float2(v00, v01);
                *(float2*)(Cf + (size_t)(r + 8) * ldc + cc) = make_float2(v10, v11);
            }
            if (Ch) {
                __half h00 = __float2half_rn(v00), h01 = __float2half_rn(v01);
                __half h10 = __float2half_rn(v10), h11 = __float2half_rn(v11);
                *(__half2*)(Ch + (size_t)r * ldc + cc)       = __halves2half2(h00, h01);
                *(__half2*)(Ch + (size_t)(r + 8) * ldc + cc) = __halves2half2(h10, h11);
            }
        }
    }
}

// q/k projection variant: writes hi AND lo pair outputs.
__global__ __launch_bounds__(512, 1)
void k_hgemm_hl(const __half* __restrict__ Ah, const __half* __restrict__ Al,
                const __half* __restrict__ Wh, const __half* __restrict__ Wl,
                const float* __restrict__ bias,
                __half* __restrict__ Ch, __half* __restrict__ Cl,
                int M, int N, int K, int lda, int ldw, int ldc)
{
    int nb = blockIdx.x, mb = blockIdx.y;
    extern __shared__ uint32_t sm32[];
    uint32_t smb = smem_u32(sm32);

    int tid  = threadIdx.x;
    int warp = tid >> 5, lane = tid & 31;
    int wm = warp >> 2, wn = warp & 3;
    int g  = lane >> 2, q4 = lane & 3;
    int m0 = mb * BM, n0 = nb * BN;
    int nch = K / KC;

    float acc[2][4][4];
    #pragma unroll
    for (int i = 0; i < 2; i++)
        #pragma unroll
        for (int j = 0; j < 4; j++)
            #pragma unroll
            for (int r = 0; r < 4; r++) acc[i][j][r] = 0.f;

    int lr  = tid >> 3;
    int seg = tid & 7;

    uint32_t a_off[2];
    #pragma unroll
    for (int tm = 0; tm < 2; tm++) {
        int row = wm * 32 + tm * 16 + (lane & 15);
        a_off[tm] = (uint32_t)(row * RS + (lane >> 4) * 4) * 4;
    }
    uint32_t b_off[2];
    #pragma unroll
    for (int p = 0; p < 2; p++) {
        int row = wn * 32 + p * 16 + (lane & 7) + ((lane >> 4) & 1) * 8;
        b_off[p] = (uint32_t)(row * RS + ((lane >> 3) & 1) * 4) * 4;
    }

    auto load_stage = [&](uint32_t sb, int kt) {
        #pragma unroll
        for (int j = 0; j < 2; j++) {
            int row = j * 64 + lr;
            uint32_t so = (uint32_t)(row * RS) * 4 + seg * 16;
            size_t ga = (size_t)(m0 + row) * lda + kt + seg * 8;
            size_t gw = (size_t)(n0 + row) * ldw + kt + seg * 8;
            cp16(sb + so,              Ah + ga);
            cp16(sb + PART4 + so,      Al + ga);
            cp16(sb + 2 * PART4 + so,  Wh + gw);
            cp16(sb + 3 * PART4 + so,  Wl + gw);
        }
    };

    load_stage(smb, 0);
    CP_COMMIT();
    if (nch > 1) { load_stage(smb + STAGE4, KC); CP_COMMIT(); }

    for (int ic = 0; ic < nch; ic++) {
        if (ic + 1 < nch) { CP_WAIT(1); } else { CP_WAIT(0); }
        __syncthreads();
        if (ic + 2 < nch) {
            load_stage(smb + (uint32_t)((ic + 2) % NSTG) * STAGE4, (ic + 2) * KC);
            CP_COMMIT();
        }
        uint32_t sbase = smb + (uint32_t)(ic % NSTG) * STAGE4;
        #pragma unroll
        for (int ks = 0; ks < 4; ks++) {
            uint32_t ko = (uint32_t)ks * 32;
            uint32_t ah[2][4], al[2][4];
            #pragma unroll
            for (int tm = 0; tm < 2; tm++) {
                LDSM4(ah[tm], sbase + a_off[tm] + ko);
                LDSM4(al[tm], sbase + PART4 + a_off[tm] + ko);
            }
            uint32_t bh[2][4], bl[2][4];
            #pragma unroll
            for (int p = 0; p < 2; p++) {
                LDSM4(bh[p], sbase + 2 * PART4 + b_off[p] + ko);
                LDSM4(bl[p], sbase + 3 * PART4 + b_off[p] + ko);
            }
            #pragma unroll
            for (int tn = 0; tn < 4; tn++) {
                const uint32_t* bhp = &bh[tn >> 1][(tn & 1) * 2];
                #pragma unroll
                for (int tm = 0; tm < 2; tm++)
                    mma16(acc[tm][tn], ah[tm], bhp);
            }
            #pragma unroll
            for (int tn = 0; tn < 4; tn++) {
                const uint32_t* blp = &bl[tn >> 1][(tn & 1) * 2];
                #pragma unroll
                for (int tm = 0; tm < 2; tm++)
                    mma16(acc[tm][tn], ah[tm], blp);
            }
            #pragma unroll
            for (int tn = 0; tn < 4; tn++) {
                const uint32_t* bhp = &bh[tn >> 1][(tn & 1) * 2];
                #pragma unroll
                for (int tm = 0; tm < 2; tm++)
                    mma16(acc[tm][tn], al[tm], bhp);
            }
        }
    }

    #pragma unroll
    for (int tm = 0; tm < 2; tm++) {
        int r = m0 + wm * 32 + tm * 16 + g;
        #pragma unroll
        for (int tn = 0; tn < 4; tn++) {
            int cc = n0 + wn * 32 + tn * 8 + q4 * 2;
            float bv0 = __ldg(bias + cc);
            float bv1 = __ldg(bias + cc + 1);
            float v00 = acc[tm][tn][0] + bv0;
            float v01 = acc[tm][tn][1] + bv1;
            float v10 = acc[tm][tn][2] + bv0;
            float v11 = acc[tm][tn][3] + bv1;
            __half h00 = __float2half_rn(v00), h01 = __float2half_rn(v01);
            __half h10 = __float2half_rn(v10), h11 = __float2half_rn(v11);
            *(__half2*)(Ch + (size_t)r * ldc + cc)       = __halves2half2(h00, h01);
            *(__half2*)(Ch + (size_t)(r + 8) * ldc + cc) = __halves2half2(h10, h11);
            *(__half2*)(Cl + (size_t)r * ldc + cc) = __halves2half2(
                __float2half_rn(v00 - __half2float(h00)),
                __float2half_rn(v01 - __half2float(h01)));
            *(__half2*)(Cl + (size_t)(r + 8) * ldc + cc) = __halves2half2(
                __float2half_rn(v10 - __half2float(h10)),
                __float2half_rn(v11 - __half2float(h11)));
        }
    }
}

// ---------------------------------------------------------------------------
// Fused prep: split x; build (0.125*Wq | Wk) and (0.125*bq | bk); split Wv, Wm.
// ---------------------------------------------------------------------------
__global__ __launch_bounds__(256)
void k_prep(const float* __restrict__ x,
            const float* __restrict__ Wq, const float* __restrict__ bq,
            const float* __restrict__ Wk, const float* __restrict__ bk,
            const float* __restrict__ Wv, const float* __restrict__ Wm)
{
    int stride = gridDim.x * 256;
    int gid = blockIdx.x * 256 + threadIdx.x;

    for (int i = gid; i < Bsz * Sq * Dd; i += stride) {
        float v = x[i];
        __half h = __float2half_rn(v);
        g_xh[i] = h;
        g_xl[i] = __float2half_rn(v - __half2float(h));
    }
    for (int i = gid; i < DW; i += stride) {
        float wq = 0.125f * Wq[i];               // exact (power of 2)
        __half h = __float2half_rn(wq);
        g_Wqkh[i] = h;
        g_Wqkl[i] = __float2half_rn(wq - __half2float(h));
        float wk = Wk[i];
        h = __float2half_rn(wk);
        g_Wqkh[DW + i] = h;
        g_Wqkl[DW + i] = __float2half_rn(wk - __half2float(h));
        float wv = Wv[i];
        h = __float2half_rn(wv);
        g_Wvh[i] = h;
        g_Wvl[i] = __float2half_rn(wv - __half2float(h));
        float wm = Wm[i];
        h = __float2half_rn(wm);
        g_Wmh[i] = h;
        g_Wml[i] = __float2half_rn(wm - __half2float(h));
    }
    for (int i = gid; i < Hh; i += stride) {
        g_bqk[i]      = 0.125f * bq[i];
        g_bqk[Hh + i] = bk[i];
    }
}

// ---------------------------------------------------------------------------
// Row softmax, single gmem read (row buffered in smem), unnormalized fp16
// probs for j in [i, S) (zeros for the in-tile prefix) + 1/rowsum.
// ---------------------------------------------------------------------------
__global__ __launch_bounds__(256)
void k_softmax(const float* __restrict__ Sc, __half* __restrict__ Ph,
               float* __restrict__ Linv)
{
    extern __shared__ float rowbuf[];
    __shared__ float red[256];
    int i = blockIdx.x;
    int b = blockIdx.y;
    size_t off = ((size_t)b * Sq + i) * Sq;
    const float* row = Sc + off;
    __half* ph = Ph + off;
    int t = threadIdx.x;

    float m = -3.402823466e38f;
    for (int j = i + t; j < Sq; j += 256) {
        float s = row[j];
        rowbuf[j] = s;
        m = fmaxf(m, s);
    }
    red[t] = m; __syncthreads();
    for (int s = 128; s > 0; s >>= 1) {
        if (t < s) red[t] = fmaxf(red[t], red[t + s]);
        __syncthreads();
    }
    m = red[0];
    __syncthreads();

    float l = 0.f;
    for (int j = i + t; j < Sq; j += 256) {
        float e = __expf(rowbuf[j] - m);
        l += e;
        ph[j] = __float2half_rn(e);
    }
    int i0 = i & ~(BM - 1);
    for (int j = i0 + t; j < i; j += 256) ph[j] = __float2half_rn(0.f);

    red[t] = l; __syncthreads();
    for (int s = 128; s > 0; s >>= 1) {
        if (t < s) red[t] += red[t + s];
        __syncthreads();
    }
    if (t == 0) Linv[(size_t)b * Sq + i] = 1.0f / red[0];
}

// ---------------------------------------------------------------------------
// Transpose v [S,H] -> vt [H,S] per batch, splitting to fp16 hi/lo.
// ---------------------------------------------------------------------------
__global__ __launch_bounds__(256)
void k_transpose_split(const float* __restrict__ V, __half* __restrict__ Th,
                       __half* __restrict__ Tl)
{
    __shared__ float t[32][33];
    int bz = blockIdx.z;
    const float* Vb = V + (size_t)bz * Sq * Hh;
    __half* Hb = Th + (size_t)bz * Sq * Hh;
    __half* Lb = Tl + (size_t)bz * Sq * Hh;
    int c0 = blockIdx.x * 32, r0 = blockIdx.y * 32;
    int tx = threadIdx.x & 31, ty = threadIdx.x >> 5;
    #pragma unroll
    for (int i = ty; i < 32; i += 8)
        t[i][tx] = Vb[(size_t)(r0 + i) * Hh + c0 + tx];
    __syncthreads();
    #pragma unroll
    for (int i = ty; i < 32; i += 8) {
        float v = t[tx][i];
        __half h = __float2half_rn(v);
        size_t o = (size_t)(c0 + i) * Sq + r0 + tx;
        Hb[o] = h;
        Lb[o] = __float2half_rn(v - __half2float(h));
    }
}

// ---------------------------------------------------------------------------
extern "C" void kernel_launch(void* const* d_in, const int* in_sizes, int n_in,
                              void* d_out, int out_size)
{
    (void)in_sizes; (void)n_in; (void)out_size;
    const float* x  = (const float*)d_in[0];
    const float* Wq = (const float*)d_in[1];
    const float* bq = (const float*)d_in[2];
    const float* Wk = (const float*)d_in[3];
    const float* bk = (const float*)d_in[4];
    const float* Wv = (const float*)d_in[5];
    const float* bv = (const float*)d_in[6];
    const float* Wm = (const float*)d_in[7];
    const float* bm = (const float*)d_in[8];
    float* out = (float*)d_out;

    __half *xh, *xl, *Wqkh, *Wqkl, *Wvh, *Wvl, *Wmh, *Wml;
    __half *qkh, *qkl, *vth, *vtl, *ph, *ath;
    float *v, *sc, *linv, *bqk;
    cudaGetSymbolAddress((void**)&xh,   g_xh);   cudaGetSymbolAddress((void**)&xl,   g_xl);
    cudaGetSymbolAddress((void**)&Wqkh, g_Wqkh); cudaGetSymbolAddress((void**)&Wqkl, g_Wqkl);
    cudaGetSymbolAddress((void**)&bqk,  g_bqk);
    cudaGetSymbolAddress((void**)&Wvh,  g_Wvh);  cudaGetSymbolAddress((void**)&Wvl,  g_Wvl);
    cudaGetSymbolAddress((void**)&Wmh,  g_Wmh);  cudaGetSymbolAddress((void**)&Wml,  g_Wml);
    cudaGetSymbolAddress((void**)&qkh,  g_qkh);  cudaGetSymbolAddress((void**)&qkl,  g_qkl);
    cudaGetSymbolAddress((void**)&v,    g_v);
    cudaGetSymbolAddress((void**)&vth,  g_vth);  cudaGetSymbolAddress((void**)&vtl,  g_vtl);
    cudaGetSymbolAddress((void**)&sc,   g_sc);
    cudaGetSymbolAddress((void**)&ph,   g_ph);
    cudaGetSymbolAddress((void**)&linv, g_linv);
    cudaGetSymbolAddress((void**)&ath,  g_ath);

    cudaFuncSetAttribute(k_hgemm,    cudaFuncAttributeMaxDynamicSharedMemorySize, SMEM_SZ);
    cudaFuncSetAttribute(k_hgemm_hl, cudaFuncAttributeMaxDynamicSharedMemorySize, SMEM_SZ);
    cudaFuncSetAttribute(k_softmax,  cudaFuncAttributeMaxDynamicSharedMemorySize, Sq * 4);

    dim3 blk(512);

    // Fused prep: split x / weights, build concat qk weight + bias.
    k_prep<<<2048, 256>>>(x, Wq, bq, Wk, bk, Wv, Wm);

    // q|k projection (one GEMM, N=1024; 0.125 folded into Wq/bq exactly).
    k_hgemm_hl<<<dim3(2 * Hh / BN, (Bsz * Sq) / BM, 1), blk, SMEM_SZ>>>(
        xh, xl, Wqkh, Wqkl, bqk, qkh, qkl,
        Bsz * Sq, 2 * Hh, Dd, Dd, Dd, 2 * Hh);

    // v projection (fp32 out).
    k_hgemm<<<dim3(Hh / BN, (Bsz * Sq) / BM, 1), blk, SMEM_SZ>>>(
        xh, xl, Wvh, Wvl, bv, (float*)0, v, (__half*)0,
        Bsz * Sq, Hh, Dd, Dd, Dd, Hh, 1.0f, 1.0f, 0, 0, 0, 0, 0);

    // Scores (fp32), upper-triangular blocks only: q/k read from qk buffer.
    k_hgemm<<<dim3(Sq / BN, Sq / BM, Bsz), blk, SMEM_SZ>>>(
        qkh, qkl, qkh + Hh, qkl + Hh, (const float*)0, (float*)0, sc, (__half*)0,
        Sq, Sq, Hh, 2 * Hh, 2 * Hh, Sq, 1.0f, 0.0f,
        (long long)Sq * 2 * Hh, (long long)Sq * 2 * Hh, (long long)Sq * Sq, 1, 0);

    // softmax -> unnormalized fp16 probs + inv rowsum.
    k_softmax<<<dim3(Sq, Bsz), 256, Sq * 4>>>(sc, ph, linv);

    // vt = v^T (split), then attn = (P @ v) * inv_l, 2-term; attn hi only.
    k_transpose_split<<<dim3(Hh / 32, Sq / 32, Bsz), 256>>>(v, vth, vtl);
    k_hgemm<<<dim3(Hh / BN, Sq / BM, Bsz), blk, SMEM_SZ>>>(
        ph, (__half*)0, vth, vtl, (const float*)0, linv, (float*)0, ath,
        Sq, Hh, Sq, Sq, Sq, Hh, 1.0f, 0.0f,
        (long long)Sq * Sq, (long long)Sq * Hh, (long long)Sq * Hh, 0, 1);

    // out = 8 * attn @ Wm^T + bm  (2-term).
    k_hgemm<<<dim3(Hh / BN, (Bsz * Sq) / BM, 1), blk, SMEM_SZ>>>(
        ath, (__half*)0, Wmh, Wml, bm, (float*)0, out, (__half*)0,
        Bsz * Sq, Hh, Dd, Dd, Dd, Hh, 8.0f, 1.0f, 0, 0, 0, 0, 0);
}